// round 4
// baseline (speedup 1.0000x reference)
#include <cuda_runtime.h>
#include <math.h>

// Problem constants
#define BATCH   8
#define DDIM    1024
#define HWSZ    1024          // 32*32
#define NVEC    8192          // BATCH * HWSZ
#define KEMB    8192
#define Z_ELEMS 8388608       // 8*1024*32*32
#define OUT_BLOCKS 4096

typedef unsigned long long ull;

// -------- device scratch (no allocations allowed) --------
__device__ ull    g_key[NVEC];
__device__ int    g_idx[NVEC];
__device__ int    g_counts[KEMB];
__device__ float  g_sum_z2[NVEC];
__device__ float  g_sum_e2[KEMB];
__device__ double g_loss_part[OUT_BLOCKS];

// packed dual-fp32 FMA: two independent rn-rounded fp32 FMAs per instruction.
__device__ __forceinline__ void ffma2(ull& d, ull a, ull b) {
    asm("fma.rn.f32x2 %0, %1, %2, %0;" : "+l"(d) : "l"(a), "l"(b));
}

__device__ __forceinline__ int swz(int u) { return u ^ ((u >> 2) & 7); }

// ======== fused pre-pass: init keys/counts + |e|^2 + |z|^2 ========
// blocks 0..1023   : sum |e_k|^2 (8 rows per block, one warp each) — arithmetic
//                    identical to prior rounds (lane-strided + shfl tree).
// blocks 1024..1055: sum |z_n|^2 (sequential c loop per row) — identical.
// blocks 1056..1087: reset g_key / g_counts.
__global__ void vq_pre_kernel(const float* __restrict__ z,
                              const float* __restrict__ e) {
    int bx = blockIdx.x;
    if (bx < 1024) {
        int warp = threadIdx.x >> 5;
        int lane = threadIdx.x & 31;
        int row  = bx * 8 + warp;
        const float* p = e + (size_t)row * DDIM;
        float s = 0.f;
        #pragma unroll 4
        for (int t = lane; t < DDIM; t += 32) {
            float v = p[t];
            s = fmaf(v, v, s);
        }
        #pragma unroll
        for (int o = 16; o > 0; o >>= 1)
            s += __shfl_down_sync(0xffffffffu, s, o);
        if (lane == 0) g_sum_e2[row] = s;
    } else if (bx < 1056) {
        int n  = (bx - 1024) * 256 + threadIdx.x;   // 0..8191
        int b  = n >> 10;
        int hw = n & 1023;
        const float* p = z + (size_t)b * (DDIM * HWSZ) + hw;
        float s = 0.f;
        #pragma unroll 8
        for (int c = 0; c < DDIM; c++) {
            float v = p[(size_t)c * HWSZ];
            s = fmaf(v, v, s);
        }
        g_sum_z2[n] = s;
    } else {
        int i = (bx - 1056) * 256 + threadIdx.x;    // 0..8191
        g_key[i] = 0xFFFFFFFFFFFFFFFFull;
        g_counts[i] = 0;
    }
}

// ======== main: fused distance GEMM (FFMA2 packed fp32) + argmin ========
// block tile 128(n) x 128(k); 256 threads; warp layout 2x4; lane 8x4; 8x8
// micro tile packed as 8x4 f32x2 pairs over k; BK=8; double-buffered smem.
// A tile stored DUPLICATED ({a,a} pairs) + XOR-swizzled for conflict-free
// ld.shared.v2.u64 broadcast-pair reads. Per-(n,k) accumulation order is
// identical to the scalar version: d strictly ascending, one fp32 acc, rn.
__global__ __launch_bounds__(256, 2)
void vq_dist_kernel(const float* __restrict__ z, const float* __restrict__ e) {
    __shared__ float As2[2][8][256];   // duplicated A, unit-swizzled
    __shared__ float Bs[2][8][128];    // B transposed [d][k]
    __shared__ ull   skey[128];

    const int tid  = threadIdx.x;
    const int warp = tid >> 5;
    const int lane = tid & 31;
    const int n0   = blockIdx.y * 128;
    const int k0   = blockIdx.x * 128;
    const int b    = n0 >> 10;          // 128 | 1024: tile within one image
    const int hw0  = n0 & 1023;
    const float* zb = z + (size_t)b * (DDIM * HWSZ) + hw0;

    // global-load mapping (BK=8)
    const int aRow = tid >> 5;            // 0..7  (d)
    const int aCol = (tid & 31) * 4;      // 0..124 (n), float4
    const int bRow = tid >> 1;            // 0..127 (k)
    const int bOff = (tid & 1) * 4;       // 0/4 (d), float4

    // duplicated-A store offsets (16B units, swizzled)
    const int c32 = tid & 31;
    const int dup0 = 4 * swz(2 * c32);
    const int dup1 = 4 * swz(2 * c32 + 1);

    // compute mapping: warp tile 64n x 32k; micro 8n x 8k
    const int nb = (warp & 1) * 64 + (lane >> 2) * 8;
    const int kb = (warp >> 1) * 32 + (lane & 3) * 8;

    // A broadcast-pair read offsets (floats, swizzled), l = 0..3
    const int ubase = (warp & 1) * 32 + (lane >> 2) * 4;
    const int offA0 = 4 * swz(ubase + 0);
    const int offA1 = 4 * swz(ubase + 1);
    const int offA2 = 4 * swz(ubase + 2);
    const int offA3 = 4 * swz(ubase + 3);

    if (tid < 128) skey[tid] = 0xFFFFFFFFFFFFFFFFull;

    ull acc[8][4];
    #pragma unroll
    for (int i = 0; i < 8; i++)
        #pragma unroll
        for (int j = 0; j < 4; j++) acc[i][j] = 0ull;

    // prologue: chunk 0 -> buffer 0
    float4 aL = *(const float4*)(zb + (size_t)aRow * HWSZ + aCol);
    float4 bL = *(const float4*)(e + (size_t)(k0 + bRow) * DDIM + bOff);
    *(float4*)&As2[0][aRow][dup0] = make_float4(aL.x, aL.x, aL.y, aL.y);
    *(float4*)&As2[0][aRow][dup1] = make_float4(aL.z, aL.z, aL.w, aL.w);
    Bs[0][bOff + 0][bRow] = bL.x;
    Bs[0][bOff + 1][bRow] = bL.y;
    Bs[0][bOff + 2][bRow] = bL.z;
    Bs[0][bOff + 3][bRow] = bL.w;
    __syncthreads();

    int buf = 0;
    #pragma unroll 1
    for (int dc = 8; dc <= DDIM; dc += 8) {
        if (dc < DDIM) {
            aL = *(const float4*)(zb + (size_t)(dc + aRow) * HWSZ + aCol);
            bL = *(const float4*)(e + (size_t)(k0 + bRow) * DDIM + dc + bOff);
        }
        #pragma unroll
        for (int dd = 0; dd < 8; dd++) {
            const float* ar = As2[buf][dd];
            ulonglong2 b0 = *(const ulonglong2*)&Bs[buf][dd][kb];
            ulonglong2 b1 = *(const ulonglong2*)&Bs[buf][dd][kb + 4];
            ulonglong2 a0 = *(const ulonglong2*)&ar[offA0];
            ulonglong2 a1 = *(const ulonglong2*)&ar[offA1];
            ulonglong2 a2 = *(const ulonglong2*)&ar[offA2];
            ulonglong2 a3 = *(const ulonglong2*)&ar[offA3];
            ull ap[8] = {a0.x, a0.y, a1.x, a1.y, a2.x, a2.y, a3.x, a3.y};
            #pragma unroll
            for (int i = 0; i < 8; i++) {
                ffma2(acc[i][0], ap[i], b0.x);
                ffma2(acc[i][1], ap[i], b0.y);
                ffma2(acc[i][2], ap[i], b1.x);
                ffma2(acc[i][3], ap[i], b1.y);
            }
        }
        if (dc < DDIM) {
            *(float4*)&As2[buf ^ 1][aRow][dup0] = make_float4(aL.x, aL.x, aL.y, aL.y);
            *(float4*)&As2[buf ^ 1][aRow][dup1] = make_float4(aL.z, aL.z, aL.w, aL.w);
            Bs[buf ^ 1][bOff + 0][bRow] = bL.x;
            Bs[buf ^ 1][bOff + 1][bRow] = bL.y;
            Bs[buf ^ 1][bOff + 2][bRow] = bL.z;
            Bs[buf ^ 1][bOff + 3][bRow] = bL.w;
            __syncthreads();
            buf ^= 1;
        }
    }

    __syncthreads();   // skey init + all compute done

    // d = fl(fl(a + b_k) - 2*acc); packed key (d_bits, k): min key ==
    // (min d, then min k) == jnp.argmin first-index tie-break (d > 0).
    #pragma unroll
    for (int i = 0; i < 8; i++) {
        int n = n0 + nb + i;
        float a = g_sum_z2[n];
        ull best = 0xFFFFFFFFFFFFFFFFull;
        #pragma unroll
        for (int jp = 0; jp < 4; jp++) {
            float s_lo = __uint_as_float((unsigned)(acc[i][jp] & 0xffffffffu));
            float s_hi = __uint_as_float((unsigned)(acc[i][jp] >> 32));
            int k = k0 + kb + 2 * jp;
            float t1 = a + g_sum_e2[k];
            float dv = t1 - 2.0f * s_lo;
            ull key = ((ull)__float_as_uint(dv) << 32) | (unsigned)k;
            best = (key < best) ? key : best;
            float t2 = a + g_sum_e2[k + 1];
            float dv2 = t2 - 2.0f * s_hi;
            ull key2 = ((ull)__float_as_uint(dv2) << 32) | (unsigned)(k + 1);
            best = (key2 < best) ? key2 : best;
        }
        atomicMin(&skey[nb + i], best);
    }
    __syncthreads();
    if (tid < 128) atomicMin(&g_key[n0 + tid], skey[tid]);
}

// ======== extract idx, build counts, optionally write idx output ========
__global__ void vq_idx_kernel(float* out_idx, int write_idx) {
    int n = blockIdx.x * blockDim.x + threadIdx.x;
    if (n >= NVEC) return;
    ull key = g_key[n];
    int idx = (int)(key & 0xFFFFFFFFull);
    g_idx[n] = idx;
    atomicAdd(&g_counts[idx], 1);
    if (write_idx) out_idx[n] = (float)idx;
}

// ======== z_q output (STE arithmetic replicated) + loss partials ========
__global__ void vq_out_kernel(const float* __restrict__ z,
                              const float* __restrict__ e,
                              float* __restrict__ out) {
    __shared__ double red[256];
    double acc = 0.0;
    #pragma unroll 1
    for (int i = blockIdx.x * 256 + threadIdx.x; i < Z_ELEMS;
         i += OUT_BLOCKS * 256) {
        int c  = (i >> 10) & 1023;
        int b  = i >> 20;
        int hw = i & 1023;
        int n  = (b << 10) | hw;
        float zq = e[(size_t)g_idx[n] * DDIM + c];
        float zv = z[i];
        float df = zq - zv;              // fp32, as in reference
        out[i] = zv + df;                // z + sg(z_q - z)
        float sq = df * df;              // fp32 square, as in reference
        acc += (double)sq;
    }
    red[threadIdx.x] = acc;
    __syncthreads();
    for (int o = 128; o > 0; o >>= 1) {
        if (threadIdx.x < o) red[threadIdx.x] += red[threadIdx.x + o];
        __syncthreads();
    }
    if (threadIdx.x == 0) g_loss_part[blockIdx.x] = red[0];
}

// ======== finalize: loss + perplexity in one single-block kernel ========
__global__ void vq_fin_kernel(float* out_loss, float* out_perp, int write) {
    __shared__ double red[1024];
    int tid = threadIdx.x;

    // ---- loss ----
    double s = 0.0;
    for (int t = 0; t < OUT_BLOCKS / 1024; t++)
        s += g_loss_part[tid * (OUT_BLOCKS / 1024) + t];
    red[tid] = s;
    __syncthreads();
    for (int o = 512; o > 0; o >>= 1) {
        if (tid < o) red[tid] += red[tid + o];
        __syncthreads();
    }
    if (tid == 0 && write) {
        double m = red[0] / (double)Z_ELEMS;
        float mf = (float)m;
        out_loss[0] = mf + 0.25f * mf;   // mean1 + BETA*mean2 (identical means)
    }
    __syncthreads();

    // ---- perplexity ----
    double p_s = 0.0;
    for (int t = 0; t < 8; t++) {
        int c = g_counts[tid * 8 + t];
        double p = (double)c * (1.0 / 8192.0);
        p_s += p * log(p + 1e-10);
    }
    red[tid] = p_s;
    __syncthreads();
    for (int o = 512; o > 0; o >>= 1) {
        if (tid < o) red[tid] += red[tid + o];
        __syncthreads();
    }
    if (tid == 0 && write) out_perp[0] = (float)exp(-red[0]);
}

extern "C" void kernel_launch(void* const* d_in, const int* in_sizes, int n_in,
                              void* d_out, int out_size) {
    const float* z = (const float*)d_in[0];
    const float* e = (const float*)d_in[1];
    float* out = (float*)d_out;

    int has_scalars = (out_size >= Z_ELEMS + 2);
    int has_idx     = (out_size >= Z_ELEMS + 2 + NVEC);

    vq_pre_kernel<<<1088, 256>>>(z, e);
    vq_dist_kernel<<<dim3(KEMB / 128, NVEC / 128), 256>>>(z, e);
    vq_idx_kernel<<<(NVEC + 255) / 256, 256>>>(
        has_idx ? out + Z_ELEMS + 2 : (float*)d_out, has_idx);
    vq_out_kernel<<<OUT_BLOCKS, 256>>>(z, e, out);
    vq_fin_kernel<<<1, 1024>>>(
        has_scalars ? out + Z_ELEMS : (float*)d_out,
        has_scalars ? out + Z_ELEMS + 1 : (float*)d_out, has_scalars);
}

// round 6
// speedup vs baseline: 1.3228x; 1.3228x over previous
#include <cuda_runtime.h>
#include <cuda_bf16.h>
#include <math.h>

// Problem constants
#define BATCH   8
#define DDIM    1024
#define HWSZ    1024          // 32*32
#define NVEC    8192          // BATCH * HWSZ
#define KEMB    8192
#define Z_ELEMS 8388608       // 8*1024*32*32
#define OUT_BLK 256           // vq_out grid
#define CAND_W  6e-4f         // candidate window (> 2*fp32 quantum + approx err)

typedef unsigned long long ull;
typedef unsigned int uint;

// -------- device scratch (static globals; no allocations) --------
__device__ float  g_S[(size_t)NVEC * KEMB];   // 268MB approx-distance matrix
__device__ uint   g_rowmin[NVEC];
__device__ int    g_cand[NVEC][32];
__device__ int    g_ccnt[NVEC];
__device__ ull    g_key[NVEC];
__device__ int    g_idx[NVEC];
__device__ int    g_counts[KEMB];
__device__ float  g_sum_z2[NVEC];
__device__ float  g_sum_e2[KEMB];
__device__ double g_loss_part[OUT_BLK];

// ---------------- PTX helpers ----------------
__device__ __forceinline__ uint smem_u32(const void* p) {
    return (uint)__cvta_generic_to_shared(p);
}
__device__ __forceinline__ void ldsm_x4_t(uint addr, uint& r0, uint& r1,
                                          uint& r2, uint& r3) {
    asm volatile("ldmatrix.sync.aligned.m8n8.x4.trans.shared.b16 {%0,%1,%2,%3}, [%4];"
                 : "=r"(r0), "=r"(r1), "=r"(r2), "=r"(r3) : "r"(addr));
}
__device__ __forceinline__ void ldsm_x4(uint addr, uint& r0, uint& r1,
                                        uint& r2, uint& r3) {
    asm volatile("ldmatrix.sync.aligned.m8n8.x4.shared.b16 {%0,%1,%2,%3}, [%4];"
                 : "=r"(r0), "=r"(r1), "=r"(r2), "=r"(r3) : "r"(addr));
}
__device__ __forceinline__ void mma16816(float* c, uint a0, uint a1, uint a2,
                                         uint a3, uint b0, uint b1) {
    asm volatile(
        "mma.sync.aligned.m16n8k16.row.col.f32.bf16.bf16.f32 "
        "{%0,%1,%2,%3}, {%4,%5,%6,%7}, {%8,%9}, {%0,%1,%2,%3};"
        : "+f"(c[0]), "+f"(c[1]), "+f"(c[2]), "+f"(c[3])
        : "r"(a0), "r"(a1), "r"(a2), "r"(a3), "r"(b0), "r"(b1));
}
__device__ __forceinline__ uint pack_bf2(float lo, float hi) {
    __nv_bfloat162 v = __floats2bfloat162_rn(lo, hi);
    return *(uint*)&v;
}

// ======== fused pre-pass: |e|^2, |z|^2 (bit-identical to proven rounds),
//          and scratch init ========
__global__ void vq_pre_kernel(const float* __restrict__ z,
                              const float* __restrict__ e) {
    int bx = blockIdx.x;
    if (bx < 1024) {
        int warp = threadIdx.x >> 5;
        int lane = threadIdx.x & 31;
        int row  = bx * 8 + warp;
        const float* p = e + (size_t)row * DDIM;
        float s = 0.f;
        #pragma unroll 4
        for (int t = lane; t < DDIM; t += 32) {
            float v = p[t];
            s = fmaf(v, v, s);
        }
        #pragma unroll
        for (int o = 16; o > 0; o >>= 1)
            s += __shfl_down_sync(0xffffffffu, s, o);
        if (lane == 0) g_sum_e2[row] = s;
    } else if (bx < 1056) {
        int n  = (bx - 1024) * 256 + threadIdx.x;   // 0..8191
        int b  = n >> 10;
        int hw = n & 1023;
        const float* p = z + (size_t)b * (DDIM * HWSZ) + hw;
        float s = 0.f;
        #pragma unroll 8
        for (int c = 0; c < DDIM; c++) {
            float v = p[(size_t)c * HWSZ];
            s = fmaf(v, v, s);
        }
        g_sum_z2[n] = s;
    } else {
        int i = (bx - 1056) * 256 + threadIdx.x;    // 0..8191
        g_counts[i] = 0;
        g_rowmin[i] = 0x7F7FFFFFu;   // FLT_MAX bits (d̂' is positive ~1)
        g_ccnt[i]   = 0;
    }
}

// ======== approx distance GEMM: bf16 tensor cores, z split hi+lo ========
// Block 128(zrow) x 128(code); 256 thr; 8 warps (4m x 2n); warp 32m x 64n.
// K-chunk = 16 d; per chunk: one B tile, A-hi and A-lo tiles, both accumulated.
// A smem [k][m] 256B rows, XOR-swizzled 16B granules -> conflict-free LDSM.trans.
// B smem [n][k] pitch 24 bf16 (48B, 16B-aligned rows; 3n mod 8 granule walk
// is already conflict-free, no XOR needed).
__global__ __launch_bounds__(256, 1)
void vq_gemm_kernel(const float* __restrict__ z, const float* __restrict__ e) {
    __shared__ __align__(16) __nv_bfloat16 Ah[2][16][128];
    __shared__ __align__(16) __nv_bfloat16 Al[2][16][128];
    __shared__ __align__(16) __nv_bfloat16 Bs[2][128][24];
    __shared__ uint smin[128];

    const int tid  = threadIdx.x;
    const int warp = tid >> 5;
    const int lane = tid & 31;
    const int g    = lane >> 2;        // mma group row
    const int t    = lane & 3;         // mma group col
    const int wm   = warp & 3;         // warp m index (4)
    const int wn   = warp >> 2;        // warp n index (2)

    const int n0z = blockIdx.y * 128;  // z-row base
    const int k0c = blockIdx.x * 128;  // code base
    const int b   = n0z >> 10;
    const int hw0 = n0z & 1023;
    const float* zb = z + (size_t)b * (DDIM * HWSZ) + hw0;

    // fill mappings
    const int fd = tid >> 4;           // 0..15: d within chunk (A fill)
    const int fj = tid & 15;           // m-octet (A fill)
    const int fn = tid >> 1;           // 0..127: code row (B fill)
    const int fh = tid & 1;            // k-half (B fill)
    const int agran = fj ^ (fd & 7);   // swizzled granule

    if (tid < 128) smin[tid] = 0xFFFFFFFFu;

    float acc[2][8][4];
    #pragma unroll
    for (int mi = 0; mi < 2; mi++)
        #pragma unroll
        for (int ni = 0; ni < 8; ni++)
            #pragma unroll
            for (int q = 0; q < 4; q++) acc[mi][ni][q] = 0.f;

    // LDSM lane addressing (byte offsets within one buffer)
    const int sel = lane >> 3, l7 = lane & 7;
    const int akrow = (sel >> 1) * 8 + l7;
    const int amoct0 = wm * 4 + 0 * 2 + (sel & 1);    // mi=0
    const int amoct1 = wm * 4 + 1 * 2 + (sel & 1);    // mi=1
    const uint aoff0 = (uint)(akrow * 256 + ((amoct0 ^ l7) * 16));
    const uint aoff1 = (uint)(akrow * 256 + ((amoct1 ^ l7) * 16));
    // B: per np (0..3): row nr = wn*64 + np*16 + (sel>>1)*8 + l7, khalf = sel&1
    int bnrow_base = wn * 64 + ((sel >> 1) * 8) + l7;
    uint boffs[4];
    #pragma unroll
    for (int np = 0; np < 4; np++) {
        int nr = bnrow_base + np * 16;
        boffs[np] = (uint)(nr * 48 + (sel & 1) * 16);
    }
    const uint Ah0 = smem_u32(&Ah[0][0][0]), Ah1 = smem_u32(&Ah[1][0][0]);
    const uint Al0 = smem_u32(&Al[0][0][0]), Al1 = smem_u32(&Al[1][0][0]);
    const uint Bs0 = smem_u32(&Bs[0][0][0]), Bs1 = smem_u32(&Bs[1][0][0]);

    // ---- prologue: load + fill chunk 0 ----
    const float* zp = zb + (size_t)fd * HWSZ + fj * 8;
    float4 zf0 = *(const float4*)zp;
    float4 zf1 = *(const float4*)(zp + 4);
    const float* ep = e + (size_t)(k0c + fn) * DDIM + fh * 8;
    float4 ef0 = *(const float4*)ep;
    float4 ef1 = *(const float4*)(ep + 4);

    {
        float zs[8] = {zf0.x, zf0.y, zf0.z, zf0.w, zf1.x, zf1.y, zf1.z, zf1.w};
        uint hp[4], lp[4];
        #pragma unroll
        for (int q = 0; q < 4; q++) {
            float a0 = zs[2*q], a1 = zs[2*q+1];
            __nv_bfloat16 h0 = __float2bfloat16(a0), h1 = __float2bfloat16(a1);
            hp[q] = ((uint)__bfloat16_as_ushort(h1) << 16) | __bfloat16_as_ushort(h0);
            lp[q] = pack_bf2(a0 - __bfloat162float(h0), a1 - __bfloat162float(h1));
        }
        *(uint4*)&Ah[0][fd][agran * 8] = make_uint4(hp[0], hp[1], hp[2], hp[3]);
        *(uint4*)&Al[0][fd][agran * 8] = make_uint4(lp[0], lp[1], lp[2], lp[3]);
        uint bp0 = pack_bf2(ef0.x, ef0.y), bp1 = pack_bf2(ef0.z, ef0.w);
        uint bp2 = pack_bf2(ef1.x, ef1.y), bp3 = pack_bf2(ef1.z, ef1.w);
        *(uint2*)&Bs[0][fn][fh * 8]     = make_uint2(bp0, bp1);
        *(uint2*)&Bs[0][fn][fh * 8 + 4] = make_uint2(bp2, bp3);
    }
    __syncthreads();

    int buf = 0;
    #pragma unroll 1
    for (int cc = 0; cc < 64; cc++) {
        if (cc < 63) {
            int dco = (cc + 1) * 16;
            const float* zp2 = zb + (size_t)(dco + fd) * HWSZ + fj * 8;
            zf0 = *(const float4*)zp2;
            zf1 = *(const float4*)(zp2 + 4);
            const float* ep2 = e + (size_t)(k0c + fn) * DDIM + dco + fh * 8;
            ef0 = *(const float4*)ep2;
            ef1 = *(const float4*)(ep2 + 4);
        }

        // ---- compute chunk cc ----
        uint Bbase = buf ? Bs1 : Bs0;
        uint bf[4][4];
        #pragma unroll
        for (int np = 0; np < 4; np++)
            ldsm_x4(Bbase + boffs[np], bf[np][0], bf[np][1], bf[np][2], bf[np][3]);

        #pragma unroll
        for (int ph = 0; ph < 2; ph++) {
            uint Abase = ph == 0 ? (buf ? Ah1 : Ah0) : (buf ? Al1 : Al0);
            uint a0[4], a1[4];
            ldsm_x4_t(Abase + aoff0, a0[0], a0[1], a0[2], a0[3]);
            ldsm_x4_t(Abase + aoff1, a1[0], a1[1], a1[2], a1[3]);
            #pragma unroll
            for (int np = 0; np < 4; np++) {
                mma16816(acc[0][2*np],   a0[0], a0[1], a0[2], a0[3], bf[np][0], bf[np][1]);
                mma16816(acc[0][2*np+1], a0[0], a0[1], a0[2], a0[3], bf[np][2], bf[np][3]);
                mma16816(acc[1][2*np],   a1[0], a1[1], a1[2], a1[3], bf[np][0], bf[np][1]);
                mma16816(acc[1][2*np+1], a1[0], a1[1], a1[2], a1[3], bf[np][2], bf[np][3]);
            }
        }

        if (cc < 63) {
            int nb = buf ^ 1;
            float zs[8] = {zf0.x, zf0.y, zf0.z, zf0.w, zf1.x, zf1.y, zf1.z, zf1.w};
            uint hp[4], lp[4];
            #pragma unroll
            for (int q = 0; q < 4; q++) {
                float v0 = zs[2*q], v1 = zs[2*q+1];
                __nv_bfloat16 h0 = __float2bfloat16(v0), h1 = __float2bfloat16(v1);
                hp[q] = ((uint)__bfloat16_as_ushort(h1) << 16) | __bfloat16_as_ushort(h0);
                lp[q] = pack_bf2(v0 - __bfloat162float(h0), v1 - __bfloat162float(h1));
            }
            *(uint4*)&Ah[nb][fd][agran * 8] = make_uint4(hp[0], hp[1], hp[2], hp[3]);
            *(uint4*)&Al[nb][fd][agran * 8] = make_uint4(lp[0], lp[1], lp[2], lp[3]);
            uint bp0 = pack_bf2(ef0.x, ef0.y), bp1 = pack_bf2(ef0.z, ef0.w);
            uint bp2 = pack_bf2(ef1.x, ef1.y), bp3 = pack_bf2(ef1.z, ef1.w);
            *(uint2*)&Bs[nb][fn][fh * 8]     = make_uint2(bp0, bp1);
            *(uint2*)&Bs[nb][fn][fh * 8 + 4] = make_uint2(bp2, bp3);
            __syncthreads();
            buf = nb;
        }
    }

    // ---- epilogue: d̂' = 1 + |e|^2 - 2ŝ; store S; row-min reduce ----
    float se2c[16];
    #pragma unroll
    for (int ni = 0; ni < 8; ni++) {
        int col = k0c + wn * 64 + ni * 8 + 2 * t;
        se2c[2*ni]     = 1.0f + g_sum_e2[col];
        se2c[2*ni + 1] = 1.0f + g_sum_e2[col + 1];
    }
    float rmin[4] = {3.4e38f, 3.4e38f, 3.4e38f, 3.4e38f};
    #pragma unroll
    for (int mi = 0; mi < 2; mi++) {
        #pragma unroll
        for (int ni = 0; ni < 8; ni++) {
            float* a = acc[mi][ni];
            float v0 = fmaf(a[0], -2.f, se2c[2*ni]);
            float v1 = fmaf(a[1], -2.f, se2c[2*ni+1]);
            float v2 = fmaf(a[2], -2.f, se2c[2*ni]);
            float v3 = fmaf(a[3], -2.f, se2c[2*ni+1]);
            int row0 = n0z + wm * 32 + mi * 16 + g;
            int col  = k0c + wn * 64 + ni * 8 + 2 * t;
            *(float2*)&g_S[(size_t)row0 * KEMB + col]       = make_float2(v0, v1);
            *(float2*)&g_S[(size_t)(row0 + 8) * KEMB + col] = make_float2(v2, v3);
            float m01 = v0 < v1 ? v0 : v1;
            float m23 = v2 < v3 ? v2 : v3;
            rmin[mi*2]   = m01 < rmin[mi*2]   ? m01 : rmin[mi*2];
            rmin[mi*2+1] = m23 < rmin[mi*2+1] ? m23 : rmin[mi*2+1];
        }
    }
    #pragma unroll
    for (int mi = 0; mi < 2; mi++) {
        atomicMin(&smin[wm * 32 + mi * 16 + g],     __float_as_uint(rmin[mi*2]));
        atomicMin(&smin[wm * 32 + mi * 16 + g + 8], __float_as_uint(rmin[mi*2+1]));
    }
    __syncthreads();
    if (tid < 128) atomicMin(&g_rowmin[n0z + tid], smin[tid]);
}

// ======== scan: collect candidates within window of row min ========
__global__ void vq_scan_kernel() {
    __shared__ int scnt;
    __shared__ int scand[32];
    int n = blockIdx.x;
    if (threadIdx.x == 0) scnt = 0;
    __syncthreads();
    float thr = __uint_as_float(g_rowmin[n]) + CAND_W;
    const float4* row = (const float4*)&g_S[(size_t)n * KEMB];
    for (int c4 = threadIdx.x; c4 < KEMB / 4; c4 += 256) {
        float4 v = row[c4];
        if (v.x <= thr) { int p = atomicAdd(&scnt, 1); if (p < 32) scand[p] = c4*4;   }
        if (v.y <= thr) { int p = atomicAdd(&scnt, 1); if (p < 32) scand[p] = c4*4+1; }
        if (v.z <= thr) { int p = atomicAdd(&scnt, 1); if (p < 32) scand[p] = c4*4+2; }
        if (v.w <= thr) { int p = atomicAdd(&scnt, 1); if (p < 32) scand[p] = c4*4+3; }
    }
    __syncthreads();
    int cnt = scnt < 32 ? scnt : 32;
    if (threadIdx.x == 0) g_ccnt[n] = cnt;
    if (threadIdx.x < cnt) g_cand[n][threadIdx.x] = scand[threadIdx.x];
}

// ======== exact verify: bitwise-identical fp32 sequential distance ========
__global__ void vq_exact_kernel(const float* __restrict__ z,
                                const float* __restrict__ e) {
    int n = blockIdx.x * 256 + threadIdx.x;
    if (n >= NVEC) return;
    int b  = n >> 10;
    int hw = n & 1023;
    const float* zp = z + (size_t)b * (DDIM * HWSZ) + hw;
    float sz = g_sum_z2[n];
    int cnt = g_ccnt[n];
    ull best = 0xFFFFFFFFFFFFFFFFull;
    for (int ci = 0; ci < cnt; ci++) {
        int k = g_cand[n][ci];
        const float* ep = e + (size_t)k * DDIM;
        float acc = 0.f;
        #pragma unroll 8
        for (int d = 0; d < DDIM; d++)
            acc = fmaf(zp[(size_t)d * HWSZ], ep[d], acc);
        float t1 = sz + g_sum_e2[k];
        float dv = t1 - 2.0f * acc;
        ull key = ((ull)__float_as_uint(dv) << 32) | (uint)k;
        best = (key < best) ? key : best;
    }
    g_key[n] = best;
}

// ======== extract idx, build counts, optionally write idx output ========
__global__ void vq_idx_kernel(float* out_idx, int write_idx) {
    int n = blockIdx.x * blockDim.x + threadIdx.x;
    if (n >= NVEC) return;
    ull key = g_key[n];
    int idx = (int)(key & 0xFFFFFFFFull);
    g_idx[n] = idx;
    atomicAdd(&g_counts[idx], 1);
    if (write_idx) out_idx[n] = (float)idx;
}

// ======== z_q output via smem transpose tile + loss partials ========
__global__ void vq_out_kernel(const float* __restrict__ z,
                              const float* __restrict__ e,
                              float* __restrict__ out) {
    __shared__ float esm[32][33];
    __shared__ int   sidx[32];
    __shared__ double red[256];
    int n0 = blockIdx.x * 32;
    int b  = n0 >> 10;
    int hw0 = n0 & 1023;
    int tx = threadIdx.x & 31;
    int ty = threadIdx.x >> 5;        // 0..7
    if (threadIdx.x < 32) sidx[threadIdx.x] = g_idx[n0 + threadIdx.x];
    double acc = 0.0;
    for (int c0 = 0; c0 < DDIM; c0 += 32) {
        __syncthreads();
        #pragma unroll
        for (int r = ty; r < 32; r += 8)
            esm[r][tx] = e[(size_t)sidx[r] * DDIM + c0 + tx];
        __syncthreads();
        #pragma unroll
        for (int cy = ty; cy < 32; cy += 8) {
            int c = c0 + cy;
            size_t oi = (size_t)b * (DDIM * HWSZ) + (size_t)c * HWSZ + hw0 + tx;
            float zv = z[oi];
            float zq = esm[tx][cy];
            float df = zq - zv;          // fp32, as in reference
            out[oi] = zv + df;           // z + sg(z_q - z)
            float sq = df * df;
            acc += (double)sq;
        }
    }
    red[threadIdx.x] = acc;
    __syncthreads();
    for (int o = 128; o > 0; o >>= 1) {
        if (threadIdx.x < o) red[threadIdx.x] += red[threadIdx.x + o];
        __syncthreads();
    }
    if (threadIdx.x == 0) g_loss_part[blockIdx.x] = red[0];
}

// ======== finalize: loss + perplexity ========
__global__ void vq_fin_kernel(float* out_loss, float* out_perp, int write) {
    __shared__ double red[1024];
    int tid = threadIdx.x;

    red[tid] = (tid < OUT_BLK) ? g_loss_part[tid] : 0.0;
    __syncthreads();
    for (int o = 512; o > 0; o >>= 1) {
        if (tid < o) red[tid] += red[tid + o];
        __syncthreads();
    }
    if (tid == 0 && write) {
        double m = red[0] / (double)Z_ELEMS;
        float mf = (float)m;
        out_loss[0] = mf + 0.25f * mf;   // mean1 + BETA*mean2 (identical means)
    }
    __syncthreads();

    double p_s = 0.0;
    for (int t = 0; t < 8; t++) {
        int c = g_counts[tid * 8 + t];
        double p = (double)c * (1.0 / 8192.0);
        p_s += p * log(p + 1e-10);
    }
    red[tid] = p_s;
    __syncthreads();
    for (int o = 512; o > 0; o >>= 1) {
        if (tid < o) red[tid] += red[tid + o];
        __syncthreads();
    }
    if (tid == 0 && write) out_perp[0] = (float)exp(-red[0]);
}

extern "C" void kernel_launch(void* const* d_in, const int* in_sizes, int n_in,
                              void* d_out, int out_size) {
    const float* z = (const float*)d_in[0];
    const float* e = (const float*)d_in[1];
    float* out = (float*)d_out;

    int has_scalars = (out_size >= Z_ELEMS + 2);
    int has_idx     = (out_size >= Z_ELEMS + 2 + NVEC);

    vq_pre_kernel<<<1088, 256>>>(z, e);
    vq_gemm_kernel<<<dim3(KEMB / 128, NVEC / 128), 256>>>(z, e);
    vq_scan_kernel<<<NVEC, 256>>>();
    vq_exact_kernel<<<NVEC / 256, 256>>>(z, e);
    vq_idx_kernel<<<NVEC / 256, 256>>>(
        has_idx ? out + Z_ELEMS + 2 : (float*)d_out, has_idx);
    vq_out_kernel<<<OUT_BLK, 256>>>(z, e, out);
    vq_fin_kernel<<<1, 1024>>>(
        has_scalars ? out + Z_ELEMS : (float*)d_out,
        has_scalars ? out + Z_ELEMS + 1 : (float*)d_out, has_scalars);
}

// round 7
// speedup vs baseline: 1.8148x; 1.3719x over previous
#include <cuda_runtime.h>
#include <cuda_bf16.h>
#include <math.h>

// Problem constants
#define BATCH   8
#define DDIM    1024
#define HWSZ    1024          // 32*32
#define NVEC    8192          // BATCH * HWSZ
#define KEMB    8192
#define Z_ELEMS 8388608       // 8*1024*32*32
#define OUT_BLK 256           // vq_out grid
#define CAND_W  6e-4f         // candidate window (> 2*fp32 quantum + approx err)

typedef unsigned long long ull;
typedef unsigned int uint;

// -------- device scratch (static globals; no allocations) --------
__device__ float  g_S[(size_t)NVEC * KEMB];   // 268MB approx-distance matrix
__device__ uint   g_rowmin[NVEC];
__device__ int    g_cand[NVEC][32];
__device__ int    g_ccnt[NVEC];
__device__ ull    g_key[NVEC];
__device__ int    g_idx[NVEC];
__device__ int    g_counts[KEMB];
__device__ float  g_sum_z2[NVEC];
__device__ float  g_sum_e2[KEMB];
__device__ double g_loss_part[OUT_BLK];

// ---------------- PTX helpers ----------------
__device__ __forceinline__ uint smem_u32(const void* p) {
    return (uint)__cvta_generic_to_shared(p);
}
__device__ __forceinline__ void ldsm_x4_t(uint addr, uint& r0, uint& r1,
                                          uint& r2, uint& r3) {
    asm volatile("ldmatrix.sync.aligned.m8n8.x4.trans.shared.b16 {%0,%1,%2,%3}, [%4];"
                 : "=r"(r0), "=r"(r1), "=r"(r2), "=r"(r3) : "r"(addr));
}
__device__ __forceinline__ void ldsm_x4(uint addr, uint& r0, uint& r1,
                                        uint& r2, uint& r3) {
    asm volatile("ldmatrix.sync.aligned.m8n8.x4.shared.b16 {%0,%1,%2,%3}, [%4];"
                 : "=r"(r0), "=r"(r1), "=r"(r2), "=r"(r3) : "r"(addr));
}
__device__ __forceinline__ void mma16816(float* c, uint a0, uint a1, uint a2,
                                         uint a3, uint b0, uint b1) {
    asm volatile(
        "mma.sync.aligned.m16n8k16.row.col.f32.bf16.bf16.f32 "
        "{%0,%1,%2,%3}, {%4,%5,%6,%7}, {%8,%9}, {%0,%1,%2,%3};"
        : "+f"(c[0]), "+f"(c[1]), "+f"(c[2]), "+f"(c[3])
        : "r"(a0), "r"(a1), "r"(a2), "r"(a3), "r"(b0), "r"(b1));
}
__device__ __forceinline__ uint pack_bf2(float lo, float hi) {
    __nv_bfloat162 v = __floats2bfloat162_rn(lo, hi);
    return *(uint*)&v;
}

// ======== fused pre-pass: |e|^2, |z|^2 (bit-identical to proven rounds),
//          and scratch init ========
__global__ void vq_pre_kernel(const float* __restrict__ z,
                              const float* __restrict__ e) {
    int bx = blockIdx.x;
    if (bx < 1024) {
        int warp = threadIdx.x >> 5;
        int lane = threadIdx.x & 31;
        int row  = bx * 8 + warp;
        const float* p = e + (size_t)row * DDIM;
        float s = 0.f;
        #pragma unroll 4
        for (int t = lane; t < DDIM; t += 32) {
            float v = p[t];
            s = fmaf(v, v, s);
        }
        #pragma unroll
        for (int o = 16; o > 0; o >>= 1)
            s += __shfl_down_sync(0xffffffffu, s, o);
        if (lane == 0) g_sum_e2[row] = s;
    } else if (bx < 1056) {
        int n  = (bx - 1024) * 256 + threadIdx.x;   // 0..8191
        int b  = n >> 10;
        int hw = n & 1023;
        const float* p = z + (size_t)b * (DDIM * HWSZ) + hw;
        float s = 0.f;
        #pragma unroll 8
        for (int c = 0; c < DDIM; c++) {
            float v = p[(size_t)c * HWSZ];
            s = fmaf(v, v, s);
        }
        g_sum_z2[n] = s;
    } else {
        int i = (bx - 1056) * 256 + threadIdx.x;    // 0..8191
        g_counts[i] = 0;
        g_rowmin[i] = 0x7F7FFFFFu;   // FLT_MAX bits (d̂' is positive ~1)
        g_ccnt[i]   = 0;
    }
}

// ======== approx distance GEMM: bf16 tensor cores, z split hi+lo ========
// Block 128(zrow) x 128(code); 256 thr; 8 warps (4m x 2n); warp 32m x 64n.
// K-chunk = 16 d; per chunk: one B tile, A-hi and A-lo tiles, both accumulated.
// A smem [k][m] 256B rows, XOR-swizzled 16B granules -> conflict-free LDSM.trans.
// B smem [n][k] pitch 24 bf16 (48B, 16B-aligned rows; 3n mod 8 granule walk
// is already conflict-free, no XOR needed).
__global__ __launch_bounds__(256, 1)
void vq_gemm_kernel(const float* __restrict__ z, const float* __restrict__ e) {
    __shared__ __align__(16) __nv_bfloat16 Ah[2][16][128];
    __shared__ __align__(16) __nv_bfloat16 Al[2][16][128];
    __shared__ __align__(16) __nv_bfloat16 Bs[2][128][24];
    __shared__ uint smin[128];

    const int tid  = threadIdx.x;
    const int warp = tid >> 5;
    const int lane = tid & 31;
    const int g    = lane >> 2;        // mma group row
    const int t    = lane & 3;         // mma group col
    const int wm   = warp & 3;         // warp m index (4)
    const int wn   = warp >> 2;        // warp n index (2)

    const int n0z = blockIdx.y * 128;  // z-row base
    const int k0c = blockIdx.x * 128;  // code base
    const int b   = n0z >> 10;
    const int hw0 = n0z & 1023;
    const float* zb = z + (size_t)b * (DDIM * HWSZ) + hw0;

    // fill mappings
    const int fd = tid >> 4;           // 0..15: d within chunk (A fill)
    const int fj = tid & 15;           // m-octet (A fill)
    const int fn = tid >> 1;           // 0..127: code row (B fill)
    const int fh = tid & 1;            // k-half (B fill)
    const int agran = fj ^ (fd & 7);   // swizzled granule

    if (tid < 128) smin[tid] = 0xFFFFFFFFu;

    float acc[2][8][4];
    #pragma unroll
    for (int mi = 0; mi < 2; mi++)
        #pragma unroll
        for (int ni = 0; ni < 8; ni++)
            #pragma unroll
            for (int q = 0; q < 4; q++) acc[mi][ni][q] = 0.f;

    // LDSM lane addressing (byte offsets within one buffer)
    const int sel = lane >> 3, l7 = lane & 7;
    const int akrow = (sel >> 1) * 8 + l7;
    const int amoct0 = wm * 4 + 0 * 2 + (sel & 1);    // mi=0
    const int amoct1 = wm * 4 + 1 * 2 + (sel & 1);    // mi=1
    const uint aoff0 = (uint)(akrow * 256 + ((amoct0 ^ l7) * 16));
    const uint aoff1 = (uint)(akrow * 256 + ((amoct1 ^ l7) * 16));
    // B: per np (0..3): row nr = wn*64 + np*16 + (sel>>1)*8 + l7, khalf = sel&1
    int bnrow_base = wn * 64 + ((sel >> 1) * 8) + l7;
    uint boffs[4];
    #pragma unroll
    for (int np = 0; np < 4; np++) {
        int nr = bnrow_base + np * 16;
        boffs[np] = (uint)(nr * 48 + (sel & 1) * 16);
    }
    const uint Ah0 = smem_u32(&Ah[0][0][0]), Ah1 = smem_u32(&Ah[1][0][0]);
    const uint Al0 = smem_u32(&Al[0][0][0]), Al1 = smem_u32(&Al[1][0][0]);
    const uint Bs0 = smem_u32(&Bs[0][0][0]), Bs1 = smem_u32(&Bs[1][0][0]);

    // ---- prologue: load + fill chunk 0 ----
    const float* zp = zb + (size_t)fd * HWSZ + fj * 8;
    float4 zf0 = *(const float4*)zp;
    float4 zf1 = *(const float4*)(zp + 4);
    const float* ep = e + (size_t)(k0c + fn) * DDIM + fh * 8;
    float4 ef0 = *(const float4*)ep;
    float4 ef1 = *(const float4*)(ep + 4);

    {
        float zs[8] = {zf0.x, zf0.y, zf0.z, zf0.w, zf1.x, zf1.y, zf1.z, zf1.w};
        uint hp[4], lp[4];
        #pragma unroll
        for (int q = 0; q < 4; q++) {
            float a0 = zs[2*q], a1 = zs[2*q+1];
            __nv_bfloat16 h0 = __float2bfloat16(a0), h1 = __float2bfloat16(a1);
            hp[q] = ((uint)__bfloat16_as_ushort(h1) << 16) | __bfloat16_as_ushort(h0);
            lp[q] = pack_bf2(a0 - __bfloat162float(h0), a1 - __bfloat162float(h1));
        }
        *(uint4*)&Ah[0][fd][agran * 8] = make_uint4(hp[0], hp[1], hp[2], hp[3]);
        *(uint4*)&Al[0][fd][agran * 8] = make_uint4(lp[0], lp[1], lp[2], lp[3]);
        uint bp0 = pack_bf2(ef0.x, ef0.y), bp1 = pack_bf2(ef0.z, ef0.w);
        uint bp2 = pack_bf2(ef1.x, ef1.y), bp3 = pack_bf2(ef1.z, ef1.w);
        *(uint2*)&Bs[0][fn][fh * 8]     = make_uint2(bp0, bp1);
        *(uint2*)&Bs[0][fn][fh * 8 + 4] = make_uint2(bp2, bp3);
    }
    __syncthreads();

    int buf = 0;
    #pragma unroll 1
    for (int cc = 0; cc < 64; cc++) {
        if (cc < 63) {
            int dco = (cc + 1) * 16;
            const float* zp2 = zb + (size_t)(dco + fd) * HWSZ + fj * 8;
            zf0 = *(const float4*)zp2;
            zf1 = *(const float4*)(zp2 + 4);
            const float* ep2 = e + (size_t)(k0c + fn) * DDIM + dco + fh * 8;
            ef0 = *(const float4*)ep2;
            ef1 = *(const float4*)(ep2 + 4);
        }

        // ---- compute chunk cc ----
        uint Bbase = buf ? Bs1 : Bs0;
        uint bf[4][4];
        #pragma unroll
        for (int np = 0; np < 4; np++)
            ldsm_x4(Bbase + boffs[np], bf[np][0], bf[np][1], bf[np][2], bf[np][3]);

        #pragma unroll
        for (int ph = 0; ph < 2; ph++) {
            uint Abase = ph == 0 ? (buf ? Ah1 : Ah0) : (buf ? Al1 : Al0);
            uint a0[4], a1[4];
            ldsm_x4_t(Abase + aoff0, a0[0], a0[1], a0[2], a0[3]);
            ldsm_x4_t(Abase + aoff1, a1[0], a1[1], a1[2], a1[3]);
            #pragma unroll
            for (int np = 0; np < 4; np++) {
                mma16816(acc[0][2*np],   a0[0], a0[1], a0[2], a0[3], bf[np][0], bf[np][1]);
                mma16816(acc[0][2*np+1], a0[0], a0[1], a0[2], a0[3], bf[np][2], bf[np][3]);
                mma16816(acc[1][2*np],   a1[0], a1[1], a1[2], a1[3], bf[np][0], bf[np][1]);
                mma16816(acc[1][2*np+1], a1[0], a1[1], a1[2], a1[3], bf[np][2], bf[np][3]);
            }
        }

        if (cc < 63) {
            int nb = buf ^ 1;
            float zs[8] = {zf0.x, zf0.y, zf0.z, zf0.w, zf1.x, zf1.y, zf1.z, zf1.w};
            uint hp[4], lp[4];
            #pragma unroll
            for (int q = 0; q < 4; q++) {
                float v0 = zs[2*q], v1 = zs[2*q+1];
                __nv_bfloat16 h0 = __float2bfloat16(v0), h1 = __float2bfloat16(v1);
                hp[q] = ((uint)__bfloat16_as_ushort(h1) << 16) | __bfloat16_as_ushort(h0);
                lp[q] = pack_bf2(v0 - __bfloat162float(h0), v1 - __bfloat162float(h1));
            }
            *(uint4*)&Ah[nb][fd][agran * 8] = make_uint4(hp[0], hp[1], hp[2], hp[3]);
            *(uint4*)&Al[nb][fd][agran * 8] = make_uint4(lp[0], lp[1], lp[2], lp[3]);
            uint bp0 = pack_bf2(ef0.x, ef0.y), bp1 = pack_bf2(ef0.z, ef0.w);
            uint bp2 = pack_bf2(ef1.x, ef1.y), bp3 = pack_bf2(ef1.z, ef1.w);
            *(uint2*)&Bs[nb][fn][fh * 8]     = make_uint2(bp0, bp1);
            *(uint2*)&Bs[nb][fn][fh * 8 + 4] = make_uint2(bp2, bp3);
            __syncthreads();
            buf = nb;
        }
    }

    // ---- epilogue: d̂' = 1 + |e|^2 - 2ŝ; store S; row-min reduce ----
    float se2c[16];
    #pragma unroll
    for (int ni = 0; ni < 8; ni++) {
        int col = k0c + wn * 64 + ni * 8 + 2 * t;
        se2c[2*ni]     = 1.0f + g_sum_e2[col];
        se2c[2*ni + 1] = 1.0f + g_sum_e2[col + 1];
    }
    float rmin[4] = {3.4e38f, 3.4e38f, 3.4e38f, 3.4e38f};
    #pragma unroll
    for (int mi = 0; mi < 2; mi++) {
        #pragma unroll
        for (int ni = 0; ni < 8; ni++) {
            float* a = acc[mi][ni];
            float v0 = fmaf(a[0], -2.f, se2c[2*ni]);
            float v1 = fmaf(a[1], -2.f, se2c[2*ni+1]);
            float v2 = fmaf(a[2], -2.f, se2c[2*ni]);
            float v3 = fmaf(a[3], -2.f, se2c[2*ni+1]);
            int row0 = n0z + wm * 32 + mi * 16 + g;
            int col  = k0c + wn * 64 + ni * 8 + 2 * t;
            *(float2*)&g_S[(size_t)row0 * KEMB + col]       = make_float2(v0, v1);
            *(float2*)&g_S[(size_t)(row0 + 8) * KEMB + col] = make_float2(v2, v3);
            float m01 = v0 < v1 ? v0 : v1;
            float m23 = v2 < v3 ? v2 : v3;
            rmin[mi*2]   = m01 < rmin[mi*2]   ? m01 : rmin[mi*2];
            rmin[mi*2+1] = m23 < rmin[mi*2+1] ? m23 : rmin[mi*2+1];
        }
    }
    #pragma unroll
    for (int mi = 0; mi < 2; mi++) {
        atomicMin(&smin[wm * 32 + mi * 16 + g],     __float_as_uint(rmin[mi*2]));
        atomicMin(&smin[wm * 32 + mi * 16 + g + 8], __float_as_uint(rmin[mi*2+1]));
    }
    __syncthreads();
    if (tid < 128) atomicMin(&g_rowmin[n0z + tid], smin[tid]);
}

// ======== scan: collect candidates within window of row min ========
__global__ void vq_scan_kernel() {
    __shared__ int scnt;
    __shared__ int scand[32];
    int n = blockIdx.x;
    if (threadIdx.x == 0) scnt = 0;
    __syncthreads();
    float thr = __uint_as_float(g_rowmin[n]) + CAND_W;
    const float4* row = (const float4*)&g_S[(size_t)n * KEMB];
    for (int c4 = threadIdx.x; c4 < KEMB / 4; c4 += 256) {
        float4 v = row[c4];
        if (v.x <= thr) { int p = atomicAdd(&scnt, 1); if (p < 32) scand[p] = c4*4;   }
        if (v.y <= thr) { int p = atomicAdd(&scnt, 1); if (p < 32) scand[p] = c4*4+1; }
        if (v.z <= thr) { int p = atomicAdd(&scnt, 1); if (p < 32) scand[p] = c4*4+2; }
        if (v.w <= thr) { int p = atomicAdd(&scnt, 1); if (p < 32) scand[p] = c4*4+3; }
    }
    __syncthreads();
    int cnt = scnt < 32 ? scnt : 32;
    if (threadIdx.x == 0) g_ccnt[n] = cnt;
    if (threadIdx.x < cnt) g_cand[n][threadIdx.x] = scand[threadIdx.x];
}

// ======== exact verify: warp per row, lane per candidate ========
// Each active lane computes the bitwise-identical fp32 sequential distance
// for its candidate: single accumulator, d strictly ascending (e via float4 ->
// 4 in-order FFMAs; z via same-address broadcast scalar loads). Winner picked
// by packed-key (d_bits, k) warp-min == jnp.argmin tie-break.
__global__ void vq_exact_kernel(const float* __restrict__ z,
                                const float* __restrict__ e) {
    int n  = blockIdx.x * 8 + (threadIdx.x >> 5);
    int ci = threadIdx.x & 31;
    int b  = n >> 10;
    int hw = n & 1023;
    const float* zp = z + (size_t)b * (DDIM * HWSZ) + hw;
    int cnt = g_ccnt[n];
    ull key = 0xFFFFFFFFFFFFFFFFull;
    if (ci < cnt) {
        int k = g_cand[n][ci];
        const float4* ep4 = (const float4*)(e + (size_t)k * DDIM);
        float acc = 0.f;
        #pragma unroll 4
        for (int d4 = 0; d4 < DDIM / 4; d4++) {
            float4 ev = ep4[d4];
            const float* zq = zp + (size_t)(4 * d4) * HWSZ;
            float z0 = zq[0];
            float z1 = zq[HWSZ];
            float z2 = zq[2 * HWSZ];
            float z3 = zq[3 * HWSZ];
            acc = fmaf(z0, ev.x, acc);
            acc = fmaf(z1, ev.y, acc);
            acc = fmaf(z2, ev.z, acc);
            acc = fmaf(z3, ev.w, acc);
        }
        float t1 = g_sum_z2[n] + g_sum_e2[k];
        float dv = t1 - 2.0f * acc;
        key = ((ull)__float_as_uint(dv) << 32) | (uint)k;
    }
    #pragma unroll
    for (int o = 16; o > 0; o >>= 1) {
        ull other = __shfl_xor_sync(0xffffffffu, key, o);
        key = other < key ? other : key;
    }
    if (ci == 0) g_key[n] = key;
}

// ======== extract idx, build counts, optionally write idx output ========
__global__ void vq_idx_kernel(float* out_idx, int write_idx) {
    int n = blockIdx.x * blockDim.x + threadIdx.x;
    if (n >= NVEC) return;
    ull key = g_key[n];
    int idx = (int)(key & 0xFFFFFFFFull);
    g_idx[n] = idx;
    atomicAdd(&g_counts[idx], 1);
    if (write_idx) out_idx[n] = (float)idx;
}

// ======== z_q output via smem transpose tile + loss partials ========
__global__ void vq_out_kernel(const float* __restrict__ z,
                              const float* __restrict__ e,
                              float* __restrict__ out) {
    __shared__ float esm[32][33];
    __shared__ int   sidx[32];
    __shared__ double red[256];
    int n0 = blockIdx.x * 32;
    int b  = n0 >> 10;
    int hw0 = n0 & 1023;
    int tx = threadIdx.x & 31;
    int ty = threadIdx.x >> 5;        // 0..7
    if (threadIdx.x < 32) sidx[threadIdx.x] = g_idx[n0 + threadIdx.x];
    double acc = 0.0;
    for (int c0 = 0; c0 < DDIM; c0 += 32) {
        __syncthreads();
        #pragma unroll
        for (int r = ty; r < 32; r += 8)
            esm[r][tx] = e[(size_t)sidx[r] * DDIM + c0 + tx];
        __syncthreads();
        #pragma unroll
        for (int cy = ty; cy < 32; cy += 8) {
            int c = c0 + cy;
            size_t oi = (size_t)b * (DDIM * HWSZ) + (size_t)c * HWSZ + hw0 + tx;
            float zv = z[oi];
            float zq = esm[tx][cy];
            float df = zq - zv;          // fp32, as in reference
            out[oi] = zv + df;           // z + sg(z_q - z)
            float sq = df * df;
            acc += (double)sq;
        }
    }
    red[threadIdx.x] = acc;
    __syncthreads();
    for (int o = 128; o > 0; o >>= 1) {
        if (threadIdx.x < o) red[threadIdx.x] += red[threadIdx.x + o];
        __syncthreads();
    }
    if (threadIdx.x == 0) g_loss_part[blockIdx.x] = red[0];
}

// ======== finalize: loss + perplexity ========
__global__ void vq_fin_kernel(float* out_loss, float* out_perp, int write) {
    __shared__ double red[1024];
    int tid = threadIdx.x;

    red[tid] = (tid < OUT_BLK) ? g_loss_part[tid] : 0.0;
    __syncthreads();
    for (int o = 512; o > 0; o >>= 1) {
        if (tid < o) red[tid] += red[tid + o];
        __syncthreads();
    }
    if (tid == 0 && write) {
        double m = red[0] / (double)Z_ELEMS;
        float mf = (float)m;
        out_loss[0] = mf + 0.25f * mf;   // mean1 + BETA*mean2 (identical means)
    }
    __syncthreads();

    double p_s = 0.0;
    for (int t = 0; t < 8; t++) {
        int c = g_counts[tid * 8 + t];
        double p = (double)c * (1.0 / 8192.0);
        p_s += p * log(p + 1e-10);
    }
    red[tid] = p_s;
    __syncthreads();
    for (int o = 512; o > 0; o >>= 1) {
        if (tid < o) red[tid] += red[tid + o];
        __syncthreads();
    }
    if (tid == 0 && write) out_perp[0] = (float)exp(-red[0]);
}

extern "C" void kernel_launch(void* const* d_in, const int* in_sizes, int n_in,
                              void* d_out, int out_size) {
    const float* z = (const float*)d_in[0];
    const float* e = (const float*)d_in[1];
    float* out = (float*)d_out;

    int has_scalars = (out_size >= Z_ELEMS + 2);
    int has_idx     = (out_size >= Z_ELEMS + 2 + NVEC);

    vq_pre_kernel<<<1088, 256>>>(z, e);
    vq_gemm_kernel<<<dim3(KEMB / 128, NVEC / 128), 256>>>(z, e);
    vq_scan_kernel<<<NVEC, 256>>>();
    vq_exact_kernel<<<NVEC / 8, 256>>>(z, e);
    vq_idx_kernel<<<NVEC / 256, 256>>>(
        has_idx ? out + Z_ELEMS + 2 : (float*)d_out, has_idx);
    vq_out_kernel<<<OUT_BLK, 256>>>(z, e, out);
    vq_fin_kernel<<<1, 1024>>>(
        has_scalars ? out + Z_ELEMS : (float*)d_out,
        has_scalars ? out + Z_ELEMS + 1 : (float*)d_out, has_scalars);
}

// round 8
// speedup vs baseline: 2.6501x; 1.4603x over previous
#include <cuda_runtime.h>
#include <cuda_bf16.h>
#include <math.h>

// Problem constants
#define BATCH   8
#define DDIM    1024
#define HWSZ    1024          // 32*32
#define NVEC    8192          // BATCH * HWSZ
#define KEMB    8192
#define Z_ELEMS 8388608       // 8*1024*32*32
#define OUT_BLK 256           // vq_out grid
#define CAND_W  1.5e-3f       // window: >= 2*bf16-gemm err bound + fp32 quantum

typedef unsigned long long ull;
typedef unsigned int uint;

// -------- device scratch (static globals; no allocations) --------
__device__ float  g_S[(size_t)NVEC * KEMB];   // 268MB approx-distance matrix
__device__ uint   g_rowmin[NVEC];
__device__ int    g_cand[NVEC][32];
__device__ int    g_ccnt[NVEC];
__device__ ull    g_key[NVEC];
__device__ int    g_idx[NVEC];
__device__ int    g_counts[KEMB];
__device__ float  g_sum_z2[NVEC];
__device__ float  g_sum_e2[KEMB];
__device__ double g_loss_part[OUT_BLK];

// ---------------- PTX helpers ----------------
__device__ __forceinline__ uint smem_u32(const void* p) {
    return (uint)__cvta_generic_to_shared(p);
}
__device__ __forceinline__ void ldsm_x4_t(uint addr, uint& r0, uint& r1,
                                          uint& r2, uint& r3) {
    asm volatile("ldmatrix.sync.aligned.m8n8.x4.trans.shared.b16 {%0,%1,%2,%3}, [%4];"
                 : "=r"(r0), "=r"(r1), "=r"(r2), "=r"(r3) : "r"(addr));
}
__device__ __forceinline__ void ldsm_x4(uint addr, uint& r0, uint& r1,
                                        uint& r2, uint& r3) {
    asm volatile("ldmatrix.sync.aligned.m8n8.x4.shared.b16 {%0,%1,%2,%3}, [%4];"
                 : "=r"(r0), "=r"(r1), "=r"(r2), "=r"(r3) : "r"(addr));
}
__device__ __forceinline__ void mma16816(float* c, uint a0, uint a1, uint a2,
                                         uint a3, uint b0, uint b1) {
    asm volatile(
        "mma.sync.aligned.m16n8k16.row.col.f32.bf16.bf16.f32 "
        "{%0,%1,%2,%3}, {%4,%5,%6,%7}, {%8,%9}, {%0,%1,%2,%3};"
        : "+f"(c[0]), "+f"(c[1]), "+f"(c[2]), "+f"(c[3])
        : "r"(a0), "r"(a1), "r"(a2), "r"(a3), "r"(b0), "r"(b1));
}
__device__ __forceinline__ uint pack_bf2(float lo, float hi) {
    __nv_bfloat162 v = __floats2bfloat162_rn(lo, hi);
    return *(uint*)&v;
}

// ======== fused pre-pass: |e|^2, |z|^2 (bit-identical to proven rounds),
//          and scratch init ========
__global__ void vq_pre_kernel(const float* __restrict__ z,
                              const float* __restrict__ e) {
    int bx = blockIdx.x;
    if (bx < 1024) {
        int warp = threadIdx.x >> 5;
        int lane = threadIdx.x & 31;
        int row  = bx * 8 + warp;
        const float* p = e + (size_t)row * DDIM;
        float s = 0.f;
        #pragma unroll 4
        for (int t = lane; t < DDIM; t += 32) {
            float v = p[t];
            s = fmaf(v, v, s);
        }
        #pragma unroll
        for (int o = 16; o > 0; o >>= 1)
            s += __shfl_down_sync(0xffffffffu, s, o);
        if (lane == 0) g_sum_e2[row] = s;
    } else if (bx < 1056) {
        int n  = (bx - 1024) * 256 + threadIdx.x;   // 0..8191
        int b  = n >> 10;
        int hw = n & 1023;
        const float* p = z + (size_t)b * (DDIM * HWSZ) + hw;
        float s = 0.f;
        #pragma unroll 8
        for (int c = 0; c < DDIM; c++) {
            float v = p[(size_t)c * HWSZ];
            s = fmaf(v, v, s);
        }
        g_sum_z2[n] = s;
    } else {
        int i = (bx - 1056) * 256 + threadIdx.x;    // 0..8191
        g_counts[i] = 0;
        g_rowmin[i] = 0x7F7FFFFFu;   // FLT_MAX bits (d̂' is positive ~1)
        g_ccnt[i]   = 0;
    }
}

// ======== approx distance GEMM: bf16 tensor cores (hi only) ========
// Block 128(zrow) x 128(code); 256 thr; 8 warps (4m x 2n); warp 32m x 64n.
// K-chunk = 16 d; per chunk: one B tile + one A tile, 16 MMAs.
// A smem [k][m] 256B rows, XOR-swizzled 16B granules -> conflict-free LDSM.trans.
// B smem [n][k] pitch 24 bf16 (48B rows, 16B-aligned).
__global__ __launch_bounds__(256, 1)
void vq_gemm_kernel(const float* __restrict__ z, const float* __restrict__ e) {
    __shared__ __align__(16) __nv_bfloat16 Ah[2][16][128];
    __shared__ __align__(16) __nv_bfloat16 Bs[2][128][24];
    __shared__ uint smin[128];

    const int tid  = threadIdx.x;
    const int warp = tid >> 5;
    const int lane = tid & 31;
    const int g    = lane >> 2;        // mma group row
    const int t    = lane & 3;         // mma group col
    const int wm   = warp & 3;         // warp m index (4)
    const int wn   = warp >> 2;        // warp n index (2)

    const int n0z = blockIdx.y * 128;  // z-row base
    const int k0c = blockIdx.x * 128;  // code base
    const int b   = n0z >> 10;
    const int hw0 = n0z & 1023;
    const float* zb = z + (size_t)b * (DDIM * HWSZ) + hw0;

    // fill mappings
    const int fd = tid >> 4;           // 0..15: d within chunk (A fill)
    const int fj = tid & 15;           // m-octet (A fill)
    const int fn = tid >> 1;           // 0..127: code row (B fill)
    const int fh = tid & 1;            // k-half (B fill)
    const int agran = fj ^ (fd & 7);   // swizzled granule

    if (tid < 128) smin[tid] = 0xFFFFFFFFu;

    float acc[2][8][4];
    #pragma unroll
    for (int mi = 0; mi < 2; mi++)
        #pragma unroll
        for (int ni = 0; ni < 8; ni++)
            #pragma unroll
            for (int q = 0; q < 4; q++) acc[mi][ni][q] = 0.f;

    // LDSM lane addressing (byte offsets within one buffer)
    const int sel = lane >> 3, l7 = lane & 7;
    const int akrow = (sel >> 1) * 8 + l7;
    const int amoct0 = wm * 4 + 0 * 2 + (sel & 1);    // mi=0
    const int amoct1 = wm * 4 + 1 * 2 + (sel & 1);    // mi=1
    const uint aoff0 = (uint)(akrow * 256 + ((amoct0 ^ l7) * 16));
    const uint aoff1 = (uint)(akrow * 256 + ((amoct1 ^ l7) * 16));
    // B: per np (0..3): row nr = wn*64 + np*16 + (sel>>1)*8 + l7, khalf = sel&1
    int bnrow_base = wn * 64 + ((sel >> 1) * 8) + l7;
    uint boffs[4];
    #pragma unroll
    for (int np = 0; np < 4; np++) {
        int nr = bnrow_base + np * 16;
        boffs[np] = (uint)(nr * 48 + (sel & 1) * 16);
    }
    const uint Ah0 = smem_u32(&Ah[0][0][0]), Ah1 = smem_u32(&Ah[1][0][0]);
    const uint Bs0 = smem_u32(&Bs[0][0][0]), Bs1 = smem_u32(&Bs[1][0][0]);

    // ---- prologue: load + fill chunk 0 ----
    const float* zp = zb + (size_t)fd * HWSZ + fj * 8;
    float4 zf0 = *(const float4*)zp;
    float4 zf1 = *(const float4*)(zp + 4);
    const float* ep = e + (size_t)(k0c + fn) * DDIM + fh * 8;
    float4 ef0 = *(const float4*)ep;
    float4 ef1 = *(const float4*)(ep + 4);

    {
        uint hp0 = pack_bf2(zf0.x, zf0.y), hp1 = pack_bf2(zf0.z, zf0.w);
        uint hp2 = pack_bf2(zf1.x, zf1.y), hp3 = pack_bf2(zf1.z, zf1.w);
        *(uint4*)&Ah[0][fd][agran * 8] = make_uint4(hp0, hp1, hp2, hp3);
        uint bp0 = pack_bf2(ef0.x, ef0.y), bp1 = pack_bf2(ef0.z, ef0.w);
        uint bp2 = pack_bf2(ef1.x, ef1.y), bp3 = pack_bf2(ef1.z, ef1.w);
        *(uint2*)&Bs[0][fn][fh * 8]     = make_uint2(bp0, bp1);
        *(uint2*)&Bs[0][fn][fh * 8 + 4] = make_uint2(bp2, bp3);
    }
    __syncthreads();

    int buf = 0;
    #pragma unroll 1
    for (int cc = 0; cc < 64; cc++) {
        if (cc < 63) {
            int dco = (cc + 1) * 16;
            const float* zp2 = zb + (size_t)(dco + fd) * HWSZ + fj * 8;
            zf0 = *(const float4*)zp2;
            zf1 = *(const float4*)(zp2 + 4);
            const float* ep2 = e + (size_t)(k0c + fn) * DDIM + dco + fh * 8;
            ef0 = *(const float4*)ep2;
            ef1 = *(const float4*)(ep2 + 4);
        }

        // ---- compute chunk cc ----
        uint Bbase = buf ? Bs1 : Bs0;
        uint bf[4][4];
        #pragma unroll
        for (int np = 0; np < 4; np++)
            ldsm_x4(Bbase + boffs[np], bf[np][0], bf[np][1], bf[np][2], bf[np][3]);

        {
            uint Abase = buf ? Ah1 : Ah0;
            uint a0[4], a1[4];
            ldsm_x4_t(Abase + aoff0, a0[0], a0[1], a0[2], a0[3]);
            ldsm_x4_t(Abase + aoff1, a1[0], a1[1], a1[2], a1[3]);
            #pragma unroll
            for (int np = 0; np < 4; np++) {
                mma16816(acc[0][2*np],   a0[0], a0[1], a0[2], a0[3], bf[np][0], bf[np][1]);
                mma16816(acc[0][2*np+1], a0[0], a0[1], a0[2], a0[3], bf[np][2], bf[np][3]);
                mma16816(acc[1][2*np],   a1[0], a1[1], a1[2], a1[3], bf[np][0], bf[np][1]);
                mma16816(acc[1][2*np+1], a1[0], a1[1], a1[2], a1[3], bf[np][2], bf[np][3]);
            }
        }

        if (cc < 63) {
            int nb = buf ^ 1;
            uint hp0 = pack_bf2(zf0.x, zf0.y), hp1 = pack_bf2(zf0.z, zf0.w);
            uint hp2 = pack_bf2(zf1.x, zf1.y), hp3 = pack_bf2(zf1.z, zf1.w);
            *(uint4*)&Ah[nb][fd][agran * 8] = make_uint4(hp0, hp1, hp2, hp3);
            uint bp0 = pack_bf2(ef0.x, ef0.y), bp1 = pack_bf2(ef0.z, ef0.w);
            uint bp2 = pack_bf2(ef1.x, ef1.y), bp3 = pack_bf2(ef1.z, ef1.w);
            *(uint2*)&Bs[nb][fn][fh * 8]     = make_uint2(bp0, bp1);
            *(uint2*)&Bs[nb][fn][fh * 8 + 4] = make_uint2(bp2, bp3);
            __syncthreads();
            buf = nb;
        }
    }

    // ---- epilogue: d̂' = 1 + |e|^2 - 2ŝ; store S; row-min reduce ----
    float se2c[16];
    #pragma unroll
    for (int ni = 0; ni < 8; ni++) {
        int col = k0c + wn * 64 + ni * 8 + 2 * t;
        se2c[2*ni]     = 1.0f + g_sum_e2[col];
        se2c[2*ni + 1] = 1.0f + g_sum_e2[col + 1];
    }
    float rmin[4] = {3.4e38f, 3.4e38f, 3.4e38f, 3.4e38f};
    #pragma unroll
    for (int mi = 0; mi < 2; mi++) {
        #pragma unroll
        for (int ni = 0; ni < 8; ni++) {
            float* a = acc[mi][ni];
            float v0 = fmaf(a[0], -2.f, se2c[2*ni]);
            float v1 = fmaf(a[1], -2.f, se2c[2*ni+1]);
            float v2 = fmaf(a[2], -2.f, se2c[2*ni]);
            float v3 = fmaf(a[3], -2.f, se2c[2*ni+1]);
            int row0 = n0z + wm * 32 + mi * 16 + g;
            int col  = k0c + wn * 64 + ni * 8 + 2 * t;
            *(float2*)&g_S[(size_t)row0 * KEMB + col]       = make_float2(v0, v1);
            *(float2*)&g_S[(size_t)(row0 + 8) * KEMB + col] = make_float2(v2, v3);
            float m01 = v0 < v1 ? v0 : v1;
            float m23 = v2 < v3 ? v2 : v3;
            rmin[mi*2]   = m01 < rmin[mi*2]   ? m01 : rmin[mi*2];
            rmin[mi*2+1] = m23 < rmin[mi*2+1] ? m23 : rmin[mi*2+1];
        }
    }
    #pragma unroll
    for (int mi = 0; mi < 2; mi++) {
        atomicMin(&smin[wm * 32 + mi * 16 + g],     __float_as_uint(rmin[mi*2]));
        atomicMin(&smin[wm * 32 + mi * 16 + g + 8], __float_as_uint(rmin[mi*2+1]));
    }
    __syncthreads();
    if (tid < 128) atomicMin(&g_rowmin[n0z + tid], smin[tid]);
}

// ======== scan: collect candidates within window of row min ========
__global__ void vq_scan_kernel() {
    __shared__ int scnt;
    __shared__ int scand[32];
    int n = blockIdx.x;
    if (threadIdx.x == 0) scnt = 0;
    __syncthreads();
    float thr = __uint_as_float(g_rowmin[n]) + CAND_W;
    const float4* row = (const float4*)&g_S[(size_t)n * KEMB];
    for (int c4 = threadIdx.x; c4 < KEMB / 4; c4 += 256) {
        float4 v = row[c4];
        if (v.x <= thr) { int p = atomicAdd(&scnt, 1); if (p < 32) scand[p] = c4*4;   }
        if (v.y <= thr) { int p = atomicAdd(&scnt, 1); if (p < 32) scand[p] = c4*4+1; }
        if (v.z <= thr) { int p = atomicAdd(&scnt, 1); if (p < 32) scand[p] = c4*4+2; }
        if (v.w <= thr) { int p = atomicAdd(&scnt, 1); if (p < 32) scand[p] = c4*4+3; }
    }
    __syncthreads();
    int cnt = scnt < 32 ? scnt : 32;
    if (threadIdx.x == 0) g_ccnt[n] = cnt;
    if (threadIdx.x < cnt) g_cand[n][threadIdx.x] = scand[threadIdx.x];
}

// ======== exact verify: warp per row, lane per candidate ========
// Bitwise-identical fp32 sequential distance per candidate; winner by packed
// (d_bits, k) warp-min == jnp.argmin first-index tie-break.
__global__ void vq_exact_kernel(const float* __restrict__ z,
                                const float* __restrict__ e) {
    int n  = blockIdx.x * 8 + (threadIdx.x >> 5);
    int ci = threadIdx.x & 31;
    int b  = n >> 10;
    int hw = n & 1023;
    const float* zp = z + (size_t)b * (DDIM * HWSZ) + hw;
    int cnt = g_ccnt[n];
    ull key = 0xFFFFFFFFFFFFFFFFull;
    if (ci < cnt) {
        int k = g_cand[n][ci];
        const float4* ep4 = (const float4*)(e + (size_t)k * DDIM);
        float acc = 0.f;
        #pragma unroll 4
        for (int d4 = 0; d4 < DDIM / 4; d4++) {
            float4 ev = ep4[d4];
            const float* zq = zp + (size_t)(4 * d4) * HWSZ;
            float z0 = zq[0];
            float z1 = zq[HWSZ];
            float z2 = zq[2 * HWSZ];
            float z3 = zq[3 * HWSZ];
            acc = fmaf(z0, ev.x, acc);
            acc = fmaf(z1, ev.y, acc);
            acc = fmaf(z2, ev.z, acc);
            acc = fmaf(z3, ev.w, acc);
        }
        float t1 = g_sum_z2[n] + g_sum_e2[k];
        float dv = t1 - 2.0f * acc;
        key = ((ull)__float_as_uint(dv) << 32) | (uint)k;
    }
    #pragma unroll
    for (int o = 16; o > 0; o >>= 1) {
        ull other = __shfl_xor_sync(0xffffffffu, key, o);
        key = other < key ? other : key;
    }
    if (ci == 0) g_key[n] = key;
}

// ======== extract idx, build counts, optionally write idx output ========
__global__ void vq_idx_kernel(float* out_idx, int write_idx) {
    int n = blockIdx.x * blockDim.x + threadIdx.x;
    if (n >= NVEC) return;
    ull key = g_key[n];
    int idx = (int)(key & 0xFFFFFFFFull);
    g_idx[n] = idx;
    atomicAdd(&g_counts[idx], 1);
    if (write_idx) out_idx[n] = (float)idx;
}

// ======== z_q output via smem transpose tile + loss partials ========
__global__ void vq_out_kernel(const float* __restrict__ z,
                              const float* __restrict__ e,
                              float* __restrict__ out) {
    __shared__ float esm[32][33];
    __shared__ int   sidx[32];
    __shared__ double red[256];
    int n0 = blockIdx.x * 32;
    int b  = n0 >> 10;
    int hw0 = n0 & 1023;
    int tx = threadIdx.x & 31;
    int ty = threadIdx.x >> 5;        // 0..7
    if (threadIdx.x < 32) sidx[threadIdx.x] = g_idx[n0 + threadIdx.x];
    double acc = 0.0;
    for (int c0 = 0; c0 < DDIM; c0 += 32) {
        __syncthreads();
        #pragma unroll
        for (int r = ty; r < 32; r += 8)
            esm[r][tx] = e[(size_t)sidx[r] * DDIM + c0 + tx];
        __syncthreads();
        #pragma unroll
        for (int cy = ty; cy < 32; cy += 8) {
            int c = c0 + cy;
            size_t oi = (size_t)b * (DDIM * HWSZ) + (size_t)c * HWSZ + hw0 + tx;
            float zv = z[oi];
            float zq = esm[tx][cy];
            float df = zq - zv;          // fp32, as in reference
            out[oi] = zv + df;           // z + sg(z_q - z)
            float sq = df * df;
            acc += (double)sq;
        }
    }
    red[threadIdx.x] = acc;
    __syncthreads();
    for (int o = 128; o > 0; o >>= 1) {
        if (threadIdx.x < o) red[threadIdx.x] += red[threadIdx.x + o];
        __syncthreads();
    }
    if (threadIdx.x == 0) g_loss_part[blockIdx.x] = red[0];
}

// ======== finalize: loss + perplexity ========
__global__ void vq_fin_kernel(float* out_loss, float* out_perp, int write) {
    __shared__ double red[1024];
    int tid = threadIdx.x;

    red[tid] = (tid < OUT_BLK) ? g_loss_part[tid] : 0.0;
    __syncthreads();
    for (int o = 512; o > 0; o >>= 1) {
        if (tid < o) red[tid] += red[tid + o];
        __syncthreads();
    }
    if (tid == 0 && write) {
        double m = red[0] / (double)Z_ELEMS;
        float mf = (float)m;
        out_loss[0] = mf + 0.25f * mf;   // mean1 + BETA*mean2 (identical means)
    }
    __syncthreads();

    double p_s = 0.0;
    for (int t = 0; t < 8; t++) {
        int c = g_counts[tid * 8 + t];
        double p = (double)c * (1.0 / 8192.0);
        p_s += p * log(p + 1e-10);
    }
    red[tid] = p_s;
    __syncthreads();
    for (int o = 512; o > 0; o >>= 1) {
        if (tid < o) red[tid] += red[tid + o];
        __syncthreads();
    }
    if (tid == 0 && write) out_perp[0] = (float)exp(-red[0]);
}

extern "C" void kernel_launch(void* const* d_in, const int* in_sizes, int n_in,
                              void* d_out, int out_size) {
    const float* z = (const float*)d_in[0];
    const float* e = (const float*)d_in[1];
    float* out = (float*)d_out;

    int has_scalars = (out_size >= Z_ELEMS + 2);
    int has_idx     = (out_size >= Z_ELEMS + 2 + NVEC);

    vq_pre_kernel<<<1088, 256>>>(z, e);
    vq_gemm_kernel<<<dim3(KEMB / 128, NVEC / 128), 256>>>(z, e);
    vq_scan_kernel<<<NVEC, 256>>>();
    vq_exact_kernel<<<NVEC / 8, 256>>>(z, e);
    vq_idx_kernel<<<NVEC / 256, 256>>>(
        has_idx ? out + Z_ELEMS + 2 : (float*)d_out, has_idx);
    vq_out_kernel<<<OUT_BLK, 256>>>(z, e, out);
    vq_fin_kernel<<<1, 1024>>>(
        has_scalars ? out + Z_ELEMS : (float*)d_out,
        has_scalars ? out + Z_ELEMS + 1 : (float*)d_out, has_scalars);
}

// round 12
// speedup vs baseline: 2.7191x; 1.0260x over previous
#include <cuda_runtime.h>
#include <cuda_bf16.h>
#include <cuda_fp16.h>
#include <math.h>

// Problem constants
#define BATCH   8
#define DDIM    1024
#define HWSZ    1024          // 32*32
#define NVEC    8192          // BATCH * HWSZ
#define KEMB    8192
#define Z_ELEMS 8388608       // 8*1024*32*32
#define OUT_BLK 256           // vq_out grid
#define CAND_W  1.5e-3f       // window: >= 2*bf16-gemm err + fp16-store err + fp32 quantum

typedef unsigned long long ull;
typedef unsigned int uint;

// -------- device scratch (static globals; no allocations) --------
__device__ __half g_S[(size_t)NVEC * KEMB];   // 134MB approx matrix: d̂'-1 in fp16
__device__ uint   g_rowmin[NVEC];             // fp32 bits of min d̂' (positive)
__device__ int    g_cand[NVEC][32];
__device__ int    g_ccnt[NVEC];
__device__ ull    g_key[NVEC];
__device__ int    g_idx[NVEC];
__device__ int    g_counts[KEMB];
__device__ float  g_sum_z2[NVEC];
__device__ float  g_sum_e2[KEMB];
__device__ double g_loss_part[OUT_BLK];

// ---------------- PTX helpers ----------------
__device__ __forceinline__ uint smem_u32(const void* p) {
    return (uint)__cvta_generic_to_shared(p);
}
__device__ __forceinline__ void ldsm_x4_t(uint addr, uint& r0, uint& r1,
                                          uint& r2, uint& r3) {
    asm volatile("ldmatrix.sync.aligned.m8n8.x4.trans.shared.b16 {%0,%1,%2,%3}, [%4];"
                 : "=r"(r0), "=r"(r1), "=r"(r2), "=r"(r3) : "r"(addr));
}
__device__ __forceinline__ void ldsm_x4(uint addr, uint& r0, uint& r1,
                                        uint& r2, uint& r3) {
    asm volatile("ldmatrix.sync.aligned.m8n8.x4.shared.b16 {%0,%1,%2,%3}, [%4];"
                 : "=r"(r0), "=r"(r1), "=r"(r2), "=r"(r3) : "r"(addr));
}
__device__ __forceinline__ void mma16816(float* c, uint a0, uint a1, uint a2,
                                         uint a3, uint b0, uint b1) {
    asm volatile(
        "mma.sync.aligned.m16n8k16.row.col.f32.bf16.bf16.f32 "
        "{%0,%1,%2,%3}, {%4,%5,%6,%7}, {%8,%9}, {%0,%1,%2,%3};"
        : "+f"(c[0]), "+f"(c[1]), "+f"(c[2]), "+f"(c[3])
        : "r"(a0), "r"(a1), "r"(a2), "r"(a3), "r"(b0), "r"(b1));
}
__device__ __forceinline__ uint pack_bf2(float lo, float hi) {
    __nv_bfloat162 v = __floats2bfloat162_rn(lo, hi);
    return *(uint*)&v;
}

// ======== fused pre-pass: |e|^2, |z|^2 (bit-identical), scratch init ========
__global__ void vq_pre_kernel(const float* __restrict__ z,
                              const float* __restrict__ e) {
    int bx = blockIdx.x;
    if (bx < 1024) {
        int warp = threadIdx.x >> 5;
        int lane = threadIdx.x & 31;
        int row  = bx * 8 + warp;
        const float* p = e + (size_t)row * DDIM;
        float s = 0.f;
        #pragma unroll 4
        for (int t = lane; t < DDIM; t += 32) {
            float v = p[t];
            s = fmaf(v, v, s);
        }
        #pragma unroll
        for (int o = 16; o > 0; o >>= 1)
            s += __shfl_down_sync(0xffffffffu, s, o);
        if (lane == 0) g_sum_e2[row] = s;
    } else if (bx < 1056) {
        int n  = (bx - 1024) * 256 + threadIdx.x;
        int b  = n >> 10;
        int hw = n & 1023;
        const float* p = z + (size_t)b * (DDIM * HWSZ) + hw;
        float s = 0.f;
        #pragma unroll 8
        for (int c = 0; c < DDIM; c++) {
            float v = p[(size_t)c * HWSZ];
            s = fmaf(v, v, s);
        }
        g_sum_z2[n] = s;
    } else {
        int i = (bx - 1056) * 256 + threadIdx.x;
        g_counts[i] = 0;
        g_rowmin[i] = 0x7F7FFFFFu;
        g_ccnt[i]   = 0;
    }
}

// ======== approx distance GEMM: bf16 tensor cores (hi only) ========
// Block 128(zrow) x 128(code); 256 thr; 8 warps (4m x 2n); warp 32m x 64n.
// K-chunk = 16 d; per chunk one B tile + one A tile, 16 MMAs/warp.
// A smem [k][m] 256B rows XOR-swizzled; B smem [n][k] pitch 24 bf16.
// occupancy 2 (regs capped at 128): cross-CTA overlap hides barriers/LDG.
__global__ __launch_bounds__(256, 2)
void vq_gemm_kernel(const float* __restrict__ z, const float* __restrict__ e) {
    __shared__ __align__(16) __nv_bfloat16 Ah[2][16][128];
    __shared__ __align__(16) __nv_bfloat16 Bs[2][128][24];
    __shared__ uint smin[128];

    const int tid  = threadIdx.x;
    const int warp = tid >> 5;
    const int lane = tid & 31;
    const int g    = lane >> 2;        // mma group row
    const int t    = lane & 3;         // mma group col
    const int wm   = warp & 3;         // warp m index (4)
    const int wn   = warp >> 2;        // warp n index (2)

    const int n0z = blockIdx.y * 128;  // z-row base
    const int k0c = blockIdx.x * 128;  // code base
    const int b   = n0z >> 10;
    const int hw0 = n0z & 1023;
    const float* zb = z + (size_t)b * (DDIM * HWSZ) + hw0;

    // fill mappings
    const int fd = tid >> 4;           // 0..15: d within chunk (A fill)
    const int fj = tid & 15;           // m-octet (A fill)
    const int fn = tid >> 1;           // 0..127: code row (B fill)
    const int fh = tid & 1;            // k-half (B fill)
    const int agran = fj ^ (fd & 7);   // swizzled granule

    if (tid < 128) smin[tid] = 0xFFFFFFFFu;

    float acc[2][8][4];
    #pragma unroll
    for (int mi = 0; mi < 2; mi++)
        #pragma unroll
        for (int ni = 0; ni < 8; ni++)
            #pragma unroll
            for (int q = 0; q < 4; q++) acc[mi][ni][q] = 0.f;

    // LDSM lane addressing (byte offsets within one buffer)
    const int sel = lane >> 3, l7 = lane & 7;
    const int akrow = (sel >> 1) * 8 + l7;
    const int amoct0 = wm * 4 + 0 * 2 + (sel & 1);    // mi=0
    const int amoct1 = wm * 4 + 1 * 2 + (sel & 1);    // mi=1
    const uint aoff0 = (uint)(akrow * 256 + ((amoct0 ^ l7) * 16));
    const uint aoff1 = (uint)(akrow * 256 + ((amoct1 ^ l7) * 16));
    int bnrow_base = wn * 64 + ((sel >> 1) * 8) + l7;
    uint boffs[4];
    #pragma unroll
    for (int np = 0; np < 4; np++) {
        int nr = bnrow_base + np * 16;
        boffs[np] = (uint)(nr * 48 + (sel & 1) * 16);
    }
    const uint Ah0 = smem_u32(&Ah[0][0][0]), Ah1 = smem_u32(&Ah[1][0][0]);
    const uint Bs0 = smem_u32(&Bs[0][0][0]), Bs1 = smem_u32(&Bs[1][0][0]);

    // ---- prologue: load + fill chunk 0 ----
    const float* zp = zb + (size_t)fd * HWSZ + fj * 8;
    float4 zf0 = *(const float4*)zp;
    float4 zf1 = *(const float4*)(zp + 4);
    const float* ep = e + (size_t)(k0c + fn) * DDIM + fh * 8;
    float4 ef0 = *(const float4*)ep;
    float4 ef1 = *(const float4*)(ep + 4);

    {
        uint hp0 = pack_bf2(zf0.x, zf0.y), hp1 = pack_bf2(zf0.z, zf0.w);
        uint hp2 = pack_bf2(zf1.x, zf1.y), hp3 = pack_bf2(zf1.z, zf1.w);
        *(uint4*)&Ah[0][fd][agran * 8] = make_uint4(hp0, hp1, hp2, hp3);
        uint bp0 = pack_bf2(ef0.x, ef0.y), bp1 = pack_bf2(ef0.z, ef0.w);
        uint bp2 = pack_bf2(ef1.x, ef1.y), bp3 = pack_bf2(ef1.z, ef1.w);
        *(uint2*)&Bs[0][fn][fh * 8]     = make_uint2(bp0, bp1);
        *(uint2*)&Bs[0][fn][fh * 8 + 4] = make_uint2(bp2, bp3);
    }
    __syncthreads();

    int buf = 0;
    #pragma unroll 1
    for (int cc = 0; cc < 64; cc++) {
        if (cc < 63) {
            int dco = (cc + 1) * 16;
            const float* zp2 = zb + (size_t)(dco + fd) * HWSZ + fj * 8;
            zf0 = *(const float4*)zp2;
            zf1 = *(const float4*)(zp2 + 4);
            const float* ep2 = e + (size_t)(k0c + fn) * DDIM + dco + fh * 8;
            ef0 = *(const float4*)ep2;
            ef1 = *(const float4*)(ep2 + 4);
        }

        // ---- compute chunk cc ----
        uint Bbase = buf ? Bs1 : Bs0;
        uint bf[4][4];
        #pragma unroll
        for (int np = 0; np < 4; np++)
            ldsm_x4(Bbase + boffs[np], bf[np][0], bf[np][1], bf[np][2], bf[np][3]);

        {
            uint Abase = buf ? Ah1 : Ah0;
            uint a0[4], a1[4];
            ldsm_x4_t(Abase + aoff0, a0[0], a0[1], a0[2], a0[3]);
            ldsm_x4_t(Abase + aoff1, a1[0], a1[1], a1[2], a1[3]);
            #pragma unroll
            for (int np = 0; np < 4; np++) {
                mma16816(acc[0][2*np],   a0[0], a0[1], a0[2], a0[3], bf[np][0], bf[np][1]);
                mma16816(acc[0][2*np+1], a0[0], a0[1], a0[2], a0[3], bf[np][2], bf[np][3]);
                mma16816(acc[1][2*np],   a1[0], a1[1], a1[2], a1[3], bf[np][0], bf[np][1]);
                mma16816(acc[1][2*np+1], a1[0], a1[1], a1[2], a1[3], bf[np][2], bf[np][3]);
            }
        }

        if (cc < 63) {
            int nb = buf ^ 1;
            uint hp0 = pack_bf2(zf0.x, zf0.y), hp1 = pack_bf2(zf0.z, zf0.w);
            uint hp2 = pack_bf2(zf1.x, zf1.y), hp3 = pack_bf2(zf1.z, zf1.w);
            *(uint4*)&Ah[nb][fd][agran * 8] = make_uint4(hp0, hp1, hp2, hp3);
            uint bp0 = pack_bf2(ef0.x, ef0.y), bp1 = pack_bf2(ef0.z, ef0.w);
            uint bp2 = pack_bf2(ef1.x, ef1.y), bp3 = pack_bf2(ef1.z, ef1.w);
            *(uint2*)&Bs[nb][fn][fh * 8]     = make_uint2(bp0, bp1);
            *(uint2*)&Bs[nb][fn][fh * 8 + 4] = make_uint2(bp2, bp3);
            __syncthreads();
            buf = nb;
        }
    }

    // ---- epilogue: v = 1 + |e|^2 - 2ŝ (fp32, for min); store v-1 as fp16 ----
    float se2c[16];
    #pragma unroll
    for (int ni = 0; ni < 8; ni++) {
        int col = k0c + wn * 64 + ni * 8 + 2 * t;
        se2c[2*ni]     = 1.0f + g_sum_e2[col];
        se2c[2*ni + 1] = 1.0f + g_sum_e2[col + 1];
    }
    float rmin[4] = {3.4e38f, 3.4e38f, 3.4e38f, 3.4e38f};
    #pragma unroll
    for (int mi = 0; mi < 2; mi++) {
        #pragma unroll
        for (int ni = 0; ni < 8; ni++) {
            float* a = acc[mi][ni];
            float v0 = fmaf(a[0], -2.f, se2c[2*ni]);
            float v1 = fmaf(a[1], -2.f, se2c[2*ni+1]);
            float v2 = fmaf(a[2], -2.f, se2c[2*ni]);
            float v3 = fmaf(a[3], -2.f, se2c[2*ni+1]);
            int row0 = n0z + wm * 32 + mi * 16 + g;
            int col  = k0c + wn * 64 + ni * 8 + 2 * t;
            __half2 h01 = __floats2half2_rn(v0 - 1.0f, v1 - 1.0f);
            __half2 h23 = __floats2half2_rn(v2 - 1.0f, v3 - 1.0f);
            *(__half2*)&g_S[(size_t)row0 * KEMB + col]       = h01;
            *(__half2*)&g_S[(size_t)(row0 + 8) * KEMB + col] = h23;
            float m01 = v0 < v1 ? v0 : v1;
            float m23 = v2 < v3 ? v2 : v3;
            rmin[mi*2]   = m01 < rmin[mi*2]   ? m01 : rmin[mi*2];
            rmin[mi*2+1] = m23 < rmin[mi*2+1] ? m23 : rmin[mi*2+1];
        }
    }
    #pragma unroll
    for (int mi = 0; mi < 2; mi++) {
        atomicMin(&smin[wm * 32 + mi * 16 + g],     __float_as_uint(rmin[mi*2]));
        atomicMin(&smin[wm * 32 + mi * 16 + g + 8], __float_as_uint(rmin[mi*2+1]));
    }
    __syncthreads();
    if (tid < 128) atomicMin(&g_rowmin[n0z + tid], smin[tid]);
}

// ======== scan: collect candidates within window of row min (fp16 S) ========
__global__ void vq_scan_kernel() {
    __shared__ int scnt;
    __shared__ int scand[32];
    int n = blockIdx.x;
    if (threadIdx.x == 0) scnt = 0;
    __syncthreads();
    // S holds v-1; compare against thr-1
    float thr = __uint_as_float(g_rowmin[n]) + CAND_W - 1.0f;
    const uint4* row = (const uint4*)&g_S[(size_t)n * KEMB];
    for (int c8 = threadIdx.x; c8 < KEMB / 8; c8 += 256) {
        uint4 u = row[c8];
        __half2 h0 = *(__half2*)&u.x, h1 = *(__half2*)&u.y;
        __half2 h2 = *(__half2*)&u.z, h3 = *(__half2*)&u.w;
        float2 f0 = __half22float2(h0), f1 = __half22float2(h1);
        float2 f2 = __half22float2(h2), f3 = __half22float2(h3);
        float vs[8] = {f0.x, f0.y, f1.x, f1.y, f2.x, f2.y, f3.x, f3.y};
        #pragma unroll
        for (int j = 0; j < 8; j++) {
            if (vs[j] <= thr) {
                int p = atomicAdd(&scnt, 1);
                if (p < 32) scand[p] = c8 * 8 + j;
            }
        }
    }
    __syncthreads();
    int cnt = scnt < 32 ? scnt : 32;
    if (threadIdx.x == 0) g_ccnt[n] = cnt;
    if (threadIdx.x < cnt) g_cand[n][threadIdx.x] = scand[threadIdx.x];
}

// ======== exact verify: warp per row, lane per candidate ========
// Bitwise-identical fp32 sequential distance per candidate; winner by packed
// (d_bits, k) warp-min == jnp.argmin first-index tie-break.
__global__ void vq_exact_kernel(const float* __restrict__ z,
                                const float* __restrict__ e) {
    int n  = blockIdx.x * 8 + (threadIdx.x >> 5);
    int ci = threadIdx.x & 31;
    int b  = n >> 10;
    int hw = n & 1023;
    const float* zp = z + (size_t)b * (DDIM * HWSZ) + hw;
    int cnt = g_ccnt[n];
    ull key = 0xFFFFFFFFFFFFFFFFull;
    if (ci < cnt) {
        int k = g_cand[n][ci];
        const float4* ep4 = (const float4*)(e + (size_t)k * DDIM);
        float acc = 0.f;
        #pragma unroll 4
        for (int d4 = 0; d4 < DDIM / 4; d4++) {
            float4 ev = ep4[d4];
            const float* zq = zp + (size_t)(4 * d4) * HWSZ;
            float z0 = zq[0];
            float z1 = zq[HWSZ];
            float z2 = zq[2 * HWSZ];
            float z3 = zq[3 * HWSZ];
            acc = fmaf(z0, ev.x, acc);
            acc = fmaf(z1, ev.y, acc);
            acc = fmaf(z2, ev.z, acc);
            acc = fmaf(z3, ev.w, acc);
        }
        float t1 = g_sum_z2[n] + g_sum_e2[k];
        float dv = t1 - 2.0f * acc;
        key = ((ull)__float_as_uint(dv) << 32) | (uint)k;
    }
    #pragma unroll
    for (int o = 16; o > 0; o >>= 1) {
        ull other = __shfl_xor_sync(0xffffffffu, key, o);
        key = other < key ? other : key;
    }
    if (ci == 0) g_key[n] = key;
}

// ======== extract idx, build counts, optionally write idx output ========
__global__ void vq_idx_kernel(float* out_idx, int write_idx) {
    int n = blockIdx.x * blockDim.x + threadIdx.x;
    if (n >= NVEC) return;
    ull key = g_key[n];
    int idx = (int)(key & 0xFFFFFFFFull);
    g_idx[n] = idx;
    atomicAdd(&g_counts[idx], 1);
    if (write_idx) out_idx[n] = (float)idx;
}

// ======== z_q output via smem transpose tile + loss partials ========
__global__ void vq_out_kernel(const float* __restrict__ z,
                              const float* __restrict__ e,
                              float* __restrict__ out) {
    __shared__ float esm[32][33];
    __shared__ int   sidx[32];
    __shared__ double red[256];
    int n0 = blockIdx.x * 32;
    int b  = n0 >> 10;
    int hw0 = n0 & 1023;
    int tx = threadIdx.x & 31;
    int ty = threadIdx.x >> 5;        // 0..7
    if (threadIdx.x < 32) sidx[threadIdx.x] = g_idx[n0 + threadIdx.x];
    double acc = 0.0;
    for (int c0 = 0; c0 < DDIM; c0 += 32) {
        __syncthreads();
        #pragma unroll
        for (int r = ty; r < 32; r += 8)
            esm[r][tx] = e[(size_t)sidx[r] * DDIM + c0 + tx];
        __syncthreads();
        #pragma unroll
        for (int cy = ty; cy < 32; cy += 8) {
            int c = c0 + cy;
            size_t oi = (size_t)b * (DDIM * HWSZ) + (size_t)c * HWSZ + hw0 + tx;
            float zv = z[oi];
            float zq = esm[tx][cy];
            float df = zq - zv;          // fp32, as in reference
            out[oi] = zv + df;           // z + sg(z_q - z)
            float sq = df * df;
            acc += (double)sq;
        }
    }
    red[threadIdx.x] = acc;
    __syncthreads();
    for (int o = 128; o > 0; o >>= 1) {
        if (threadIdx.x < o) red[threadIdx.x] += red[threadIdx.x + o];
        __syncthreads();
    }
    if (threadIdx.x == 0) g_loss_part[blockIdx.x] = red[0];
}

// ======== finalize: loss + perplexity ========
__global__ void vq_fin_kernel(float* out_loss, float* out_perp, int write) {
    __shared__ double red[1024];
    int tid = threadIdx.x;

    red[tid] = (tid < OUT_BLK) ? g_loss_part[tid] : 0.0;
    __syncthreads();
    for (int o = 512; o > 0; o >>= 1) {
        if (tid < o) red[tid] += red[tid + o];
        __syncthreads();
    }
    if (tid == 0 && write) {
        double m = red[0] / (double)Z_ELEMS;
        float mf = (float)m;
        out_loss[0] = mf + 0.25f * mf;   // mean1 + BETA*mean2 (identical means)
    }
    __syncthreads();

    double p_s = 0.0;
    for (int t = 0; t < 8; t++) {
        int c = g_counts[tid * 8 + t];
        double p = (double)c * (1.0 / 8192.0);
        p_s += p * log(p + 1e-10);
    }
    red[tid] = p_s;
    __syncthreads();
    for (int o = 512; o > 0; o >>= 1) {
        if (tid < o) red[tid] += red[tid + o];
        __syncthreads();
    }
    if (tid == 0 && write) out_perp[0] = (float)exp(-red[0]);
}

extern "C" void kernel_launch(void* const* d_in, const int* in_sizes, int n_in,
                              void* d_out, int out_size) {
    const float* z = (const float*)d_in[0];
    const float* e = (const float*)d_in[1];
    float* out = (float*)d_out;

    int has_scalars = (out_size >= Z_ELEMS + 2);
    int has_idx     = (out_size >= Z_ELEMS + 2 + NVEC);

    vq_pre_kernel<<<1088, 256>>>(z, e);
    vq_gemm_kernel<<<dim3(KEMB / 128, NVEC / 128), 256>>>(z, e);
    vq_scan_kernel<<<NVEC, 256>>>();
    vq_exact_kernel<<<NVEC / 8, 256>>>(z, e);
    vq_idx_kernel<<<NVEC / 256, 256>>>(
        has_idx ? out + Z_ELEMS + 2 : (float*)d_out, has_idx);
    vq_out_kernel<<<OUT_BLK, 256>>>(z, e, out);
    vq_fin_kernel<<<1, 1024>>>(
        has_scalars ? out + Z_ELEMS : (float*)d_out,
        has_scalars ? out + Z_ELEMS + 1 : (float*)d_out, has_scalars);
}

// round 14
// speedup vs baseline: 3.4598x; 1.2724x over previous
#include <cuda_runtime.h>
#include <cuda_bf16.h>
#include <cuda_fp16.h>
#include <math.h>

// Problem constants
#define BATCH   8
#define DDIM    1024
#define HWSZ    1024          // 32*32
#define NVEC    8192          // BATCH * HWSZ
#define KEMB    8192
#define Z_ELEMS 8388608       // 8*1024*32*32
#define OUT_BLK 256           // vq_out grid
#define CAND_W  1.5e-3f       // window: >= 2*bf16-gemm err + fp16-store err + fp32 quantum

typedef unsigned long long ull;
typedef unsigned int uint;

// -------- device scratch (static globals; no allocations) --------
__device__ __half g_S[(size_t)NVEC * KEMB];   // 134MB approx matrix: d̂'-1 in fp16
__device__ __nv_bfloat16 g_zT[(size_t)NVEC * DDIM];   // z transposed, bf16
__device__ __nv_bfloat16 g_ebf[(size_t)KEMB * DDIM];  // e, bf16
__device__ float  g_zTf[(size_t)NVEC * DDIM];         // z transposed, fp32 (exact bits)
__device__ uint   g_rowmin[NVEC];             // fp32 bits of min d̂' (positive)
__device__ int    g_cand[NVEC][32];
__device__ int    g_ccnt[NVEC];
__device__ ull    g_key[NVEC];
__device__ int    g_idx[NVEC];
__device__ int    g_counts[KEMB];
__device__ float  g_sum_z2[NVEC];
__device__ float  g_sum_e2[KEMB];
__device__ double g_loss_part[OUT_BLK];

// ---------------- PTX helpers ----------------
__device__ __forceinline__ uint smem_u32(const void* p) {
    return (uint)__cvta_generic_to_shared(p);
}
__device__ __forceinline__ void ldsm_x4(uint addr, uint& r0, uint& r1,
                                        uint& r2, uint& r3) {
    asm volatile("ldmatrix.sync.aligned.m8n8.x4.shared.b16 {%0,%1,%2,%3}, [%4];"
                 : "=r"(r0), "=r"(r1), "=r"(r2), "=r"(r3) : "r"(addr));
}
__device__ __forceinline__ void mma16816(float* c, uint a0, uint a1, uint a2,
                                         uint a3, uint b0, uint b1) {
    asm volatile(
        "mma.sync.aligned.m16n8k16.row.col.f32.bf16.bf16.f32 "
        "{%0,%1,%2,%3}, {%4,%5,%6,%7}, {%8,%9}, {%0,%1,%2,%3};"
        : "+f"(c[0]), "+f"(c[1]), "+f"(c[2]), "+f"(c[3])
        : "r"(a0), "r"(a1), "r"(a2), "r"(a3), "r"(b0), "r"(b1));
}
__device__ __forceinline__ void cp16(uint dst, const void* src) {
    asm volatile("cp.async.cg.shared.global [%0], [%1], 16;"
                 :: "r"(dst), "l"(src) : "memory");
}
__device__ __forceinline__ uint pack_bf2(float lo, float hi) {
    __nv_bfloat162 v = __floats2bfloat162_rn(lo, hi);
    return *(uint*)&v;
}

// ======== fused pre-pass: |e|^2, |z|^2 (bit-identical), init, bf16/fp32 prep =
// [0,1024)     : sum |e_k|^2
// [1024,1056)  : sum |z_n|^2
// [1056,1088)  : init counts/rowmin/ccnt
// [1088,3136)  : e -> bf16 (g_ebf)
// [3136,11328) : z transpose -> g_zTf (fp32, exact bits) + g_zT (bf16)
__global__ void vq_pre_kernel(const float* __restrict__ z,
                              const float* __restrict__ e) {
    __shared__ float sm[32][33];
    int bx = blockIdx.x;
    if (bx < 1024) {
        int warp = threadIdx.x >> 5;
        int lane = threadIdx.x & 31;
        int row  = bx * 8 + warp;
        const float* p = e + (size_t)row * DDIM;
        float s = 0.f;
        #pragma unroll 4
        for (int t = lane; t < DDIM; t += 32) {
            float v = p[t];
            s = fmaf(v, v, s);
        }
        #pragma unroll
        for (int o = 16; o > 0; o >>= 1)
            s += __shfl_down_sync(0xffffffffu, s, o);
        if (lane == 0) g_sum_e2[row] = s;
    } else if (bx < 1056) {
        int n  = (bx - 1024) * 256 + threadIdx.x;
        int b  = n >> 10;
        int hw = n & 1023;
        const float* p = z + (size_t)b * (DDIM * HWSZ) + hw;
        float s = 0.f;
        #pragma unroll 8
        for (int c = 0; c < DDIM; c++) {
            float v = p[(size_t)c * HWSZ];
            s = fmaf(v, v, s);
        }
        g_sum_z2[n] = s;
    } else if (bx < 1088) {
        int i = (bx - 1056) * 256 + threadIdx.x;
        g_counts[i] = 0;
        g_rowmin[i] = 0x7F7FFFFFu;
        g_ccnt[i]   = 0;
    } else if (bx < 3136) {
        size_t base = ((size_t)(bx - 1088) * 256 + threadIdx.x) * 16;
        const float4* src = (const float4*)(e + base);
        float4 f0 = src[0], f1 = src[1], f2 = src[2], f3 = src[3];
        uint u[8];
        u[0] = pack_bf2(f0.x, f0.y); u[1] = pack_bf2(f0.z, f0.w);
        u[2] = pack_bf2(f1.x, f1.y); u[3] = pack_bf2(f1.z, f1.w);
        u[4] = pack_bf2(f2.x, f2.y); u[5] = pack_bf2(f2.z, f2.w);
        u[6] = pack_bf2(f3.x, f3.y); u[7] = pack_bf2(f3.z, f3.w);
        uint4* dst = (uint4*)(g_ebf + base);
        dst[0] = make_uint4(u[0], u[1], u[2], u[3]);
        dst[1] = make_uint4(u[4], u[5], u[6], u[7]);
    } else {
        // z transpose 32x32 tile: [b][c][hw] -> [n][d]
        int t = bx - 3136;                 // 0..8191
        int b   = t >> 10;
        int rem = t & 1023;
        int ct  = (rem >> 5) * 32;
        int hwt = (rem & 31) * 32;
        int tx = threadIdx.x & 31;
        int ty = threadIdx.x >> 5;         // 0..7
        #pragma unroll
        for (int r = ty; r < 32; r += 8)
            sm[r][tx] = z[((size_t)b * DDIM + ct + r) * HWSZ + hwt + tx];
        __syncthreads();
        #pragma unroll
        for (int r = ty; r < 32; r += 8) {
            float v = sm[tx][r];
            size_t o = ((size_t)b * 1024 + hwt + r) * DDIM + ct + tx;
            g_zTf[o] = v;
            g_zT[o]  = __float2bfloat16(v);
        }
    }
}

// ======== approx distance GEMM: bf16 mma.sync + 4-stage cp.async ========
// Block 128(zrow) x 128(code); 256 thr; 8 warps (4m x 2n); warp 32m x 64n.
// Both A and B tiles [128][24] bf16 (48B rows, 16B-aligned; 3r mod 8 granule
// walk -> conflict-free non-trans LDSM for both operands).
// 4-stage cp.async pipeline, one __syncthreads per chunk.
__global__ __launch_bounds__(256, 2)
void vq_gemm_kernel() {
    __shared__ __align__(16) __nv_bfloat16 As[4][128][24];
    __shared__ __align__(16) __nv_bfloat16 Bs[4][128][24];
    uint* smin = (uint*)&As[0][0][0];   // aliased; used only in epilogue

    const int tid  = threadIdx.x;
    const int warp = tid >> 5;
    const int lane = tid & 31;
    const int g    = lane >> 2;
    const int t    = lane & 3;
    const int wm   = warp & 3;
    const int wn   = warp >> 2;

    const int n0z = blockIdx.y * 128;
    const int k0c = blockIdx.x * 128;

    // fill mapping: thread -> (row = tid>>1, khalf = tid&1), 16B per stage
    const int frow = tid >> 1;
    const int fkh  = tid & 1;
    const uint dstoff = (uint)(frow * 48 + fkh * 16);
    const __nv_bfloat16* srcA = g_zT  + (size_t)(n0z + frow) * DDIM + fkh * 8;
    const __nv_bfloat16* srcB = g_ebf + (size_t)(k0c + frow) * DDIM + fkh * 8;

    const uint A0 = smem_u32(&As[0][0][0]);
    const uint B0 = smem_u32(&Bs[0][0][0]);

    // LDSM addressing
    const int sel = lane >> 3, l7 = lane & 7;
    const uint aoff0 = (uint)((wm * 32 +  0 + (sel & 1) * 8 + l7) * 48 + (sel >> 1) * 16);
    const uint aoff1 = (uint)((wm * 32 + 16 + (sel & 1) * 8 + l7) * 48 + (sel >> 1) * 16);
    uint boffs[4];
    #pragma unroll
    for (int np = 0; np < 4; np++) {
        int nr = wn * 64 + np * 16 + ((sel >> 1) * 8) + l7;
        boffs[np] = (uint)(nr * 48 + (sel & 1) * 16);
    }

    float acc[2][8][4];
    #pragma unroll
    for (int mi = 0; mi < 2; mi++)
        #pragma unroll
        for (int ni = 0; ni < 8; ni++)
            #pragma unroll
            for (int q = 0; q < 4; q++) acc[mi][ni][q] = 0.f;

    // prologue: stages 0..2
    #pragma unroll
    for (int s = 0; s < 3; s++) {
        cp16(A0 + s * 6144 + dstoff, srcA + s * 16);
        cp16(B0 + s * 6144 + dstoff, srcB + s * 16);
        asm volatile("cp.async.commit_group;" ::: "memory");
    }

    #pragma unroll 1
    for (int cc = 0; cc < 64; cc++) {
        const int buf = cc & 3;
        asm volatile("cp.async.wait_group 2;" ::: "memory");
        __syncthreads();

        uint Ab = A0 + buf * 6144;
        uint Bb = B0 + buf * 6144;
        uint bf[4][4];
        #pragma unroll
        for (int np = 0; np < 4; np++)
            ldsm_x4(Bb + boffs[np], bf[np][0], bf[np][1], bf[np][2], bf[np][3]);
        uint a0[4], a1[4];
        ldsm_x4(Ab + aoff0, a0[0], a0[1], a0[2], a0[3]);
        ldsm_x4(Ab + aoff1, a1[0], a1[1], a1[2], a1[3]);
        #pragma unroll
        for (int np = 0; np < 4; np++) {
            mma16816(acc[0][2*np],   a0[0], a0[1], a0[2], a0[3], bf[np][0], bf[np][1]);
            mma16816(acc[0][2*np+1], a0[0], a0[1], a0[2], a0[3], bf[np][2], bf[np][3]);
            mma16816(acc[1][2*np],   a1[0], a1[1], a1[2], a1[3], bf[np][0], bf[np][1]);
            mma16816(acc[1][2*np+1], a1[0], a1[1], a1[2], a1[3], bf[np][2], bf[np][3]);
        }

        if (cc < 61) {
            int s = cc + 3;
            cp16(A0 + (s & 3) * 6144 + dstoff, srcA + s * 16);
            cp16(B0 + (s & 3) * 6144 + dstoff, srcB + s * 16);
        }
        asm volatile("cp.async.commit_group;" ::: "memory");
    }

    // ---- epilogue: v = 1 + |e|^2 - 2ŝ; store v-1 fp16; row-min reduce ----
    if (tid < 128) smin[tid] = 0xFFFFFFFFu;   // As[0] no longer read
    __syncthreads();

    float se2c[16];
    #pragma unroll
    for (int ni = 0; ni < 8; ni++) {
        int col = k0c + wn * 64 + ni * 8 + 2 * t;
        se2c[2*ni]     = 1.0f + g_sum_e2[col];
        se2c[2*ni + 1] = 1.0f + g_sum_e2[col + 1];
    }
    float rmin[4] = {3.4e38f, 3.4e38f, 3.4e38f, 3.4e38f};
    #pragma unroll
    for (int mi = 0; mi < 2; mi++) {
        #pragma unroll
        for (int ni = 0; ni < 8; ni++) {
            float* a = acc[mi][ni];
            float v0 = fmaf(a[0], -2.f, se2c[2*ni]);
            float v1 = fmaf(a[1], -2.f, se2c[2*ni+1]);
            float v2 = fmaf(a[2], -2.f, se2c[2*ni]);
            float v3 = fmaf(a[3], -2.f, se2c[2*ni+1]);
            int row0 = n0z + wm * 32 + mi * 16 + g;
            int col  = k0c + wn * 64 + ni * 8 + 2 * t;
            __half2 h01 = __floats2half2_rn(v0 - 1.0f, v1 - 1.0f);
            __half2 h23 = __floats2half2_rn(v2 - 1.0f, v3 - 1.0f);
            *(__half2*)&g_S[(size_t)row0 * KEMB + col]       = h01;
            *(__half2*)&g_S[(size_t)(row0 + 8) * KEMB + col] = h23;
            float m01 = v0 < v1 ? v0 : v1;
            float m23 = v2 < v3 ? v2 : v3;
            rmin[mi*2]   = m01 < rmin[mi*2]   ? m01 : rmin[mi*2];
            rmin[mi*2+1] = m23 < rmin[mi*2+1] ? m23 : rmin[mi*2+1];
        }
    }
    #pragma unroll
    for (int mi = 0; mi < 2; mi++) {
        atomicMin(&smin[wm * 32 + mi * 16 + g],     __float_as_uint(rmin[mi*2]));
        atomicMin(&smin[wm * 32 + mi * 16 + g + 8], __float_as_uint(rmin[mi*2+1]));
    }
    __syncthreads();
    if (tid < 128) atomicMin(&g_rowmin[n0z + tid], smin[tid]);
}

// ======== scan: collect candidates within window of row min (fp16 S) ========
__global__ void vq_scan_kernel() {
    __shared__ int scnt;
    __shared__ int scand[32];
    int n = blockIdx.x;
    if (threadIdx.x == 0) scnt = 0;
    __syncthreads();
    float thr = __uint_as_float(g_rowmin[n]) + CAND_W - 1.0f;
    const uint4* row = (const uint4*)&g_S[(size_t)n * KEMB];
    for (int c8 = threadIdx.x; c8 < KEMB / 8; c8 += 256) {
        uint4 u = row[c8];
        __half2 h0 = *(__half2*)&u.x, h1 = *(__half2*)&u.y;
        __half2 h2 = *(__half2*)&u.z, h3 = *(__half2*)&u.w;
        float2 f0 = __half22float2(h0), f1 = __half22float2(h1);
        float2 f2 = __half22float2(h2), f3 = __half22float2(h3);
        float vs[8] = {f0.x, f0.y, f1.x, f1.y, f2.x, f2.y, f3.x, f3.y};
        #pragma unroll
        for (int j = 0; j < 8; j++) {
            if (vs[j] <= thr) {
                int p = atomicAdd(&scnt, 1);
                if (p < 32) scand[p] = c8 * 8 + j;
            }
        }
    }
    __syncthreads();
    int cnt = scnt < 32 ? scnt : 32;
    if (threadIdx.x == 0) g_ccnt[n] = cnt;
    if (threadIdx.x < cnt) g_cand[n][threadIdx.x] = scand[threadIdx.x];
}

// ======== exact verify: warp per row, lane per candidate ========
// Bitwise-identical fp32 sequential distance (z from g_zTf: same bits,
// contiguous layout; float4 in-order FFMAs). Winner by packed (d_bits, k)
// warp-min == jnp.argmin first-index tie-break.
__global__ void vq_exact_kernel(const float* __restrict__ e) {
    int n  = blockIdx.x * 8 + (threadIdx.x >> 5);
    int ci = threadIdx.x & 31;
    const float4* zr4 = (const float4*)(g_zTf + (size_t)n * DDIM);
    int cnt = g_ccnt[n];
    ull key = 0xFFFFFFFFFFFFFFFFull;
    if (ci < cnt) {
        int k = g_cand[n][ci];
        const float4* er4 = (const float4*)(e + (size_t)k * DDIM);
        float acc = 0.f;
        #pragma unroll 4
        for (int d4 = 0; d4 < DDIM / 4; d4++) {
            float4 zv = zr4[d4];
            float4 ev = er4[d4];
            acc = fmaf(zv.x, ev.x, acc);
            acc = fmaf(zv.y, ev.y, acc);
            acc = fmaf(zv.z, ev.z, acc);
            acc = fmaf(zv.w, ev.w, acc);
        }
        float t1 = g_sum_z2[n] + g_sum_e2[k];
        float dv = t1 - 2.0f * acc;
        key = ((ull)__float_as_uint(dv) << 32) | (uint)k;
    }
    #pragma unroll
    for (int o = 16; o > 0; o >>= 1) {
        ull other = __shfl_xor_sync(0xffffffffu, key, o);
        key = other < key ? other : key;
    }
    if (ci == 0) g_key[n] = key;
}

// ======== extract idx, build counts, optionally write idx output ========
__global__ void vq_idx_kernel(float* out_idx, int write_idx) {
    int n = blockIdx.x * blockDim.x + threadIdx.x;
    if (n >= NVEC) return;
    ull key = g_key[n];
    int idx = (int)(key & 0xFFFFFFFFull);
    g_idx[n] = idx;
    atomicAdd(&g_counts[idx], 1);
    if (write_idx) out_idx[n] = (float)idx;
}

// ======== z_q output via smem transpose tile + loss partials ========
__global__ void vq_out_kernel(const float* __restrict__ z,
                              const float* __restrict__ e,
                              float* __restrict__ out) {
    __shared__ float esm[32][33];
    __shared__ int   sidx[32];
    __shared__ double red[256];
    int n0 = blockIdx.x * 32;
    int b  = n0 >> 10;
    int hw0 = n0 & 1023;
    int tx = threadIdx.x & 31;
    int ty = threadIdx.x >> 5;
    if (threadIdx.x < 32) sidx[threadIdx.x] = g_idx[n0 + threadIdx.x];
    double acc = 0.0;
    for (int c0 = 0; c0 < DDIM; c0 += 32) {
        __syncthreads();
        #pragma unroll
        for (int r = ty; r < 32; r += 8)
            esm[r][tx] = e[(size_t)sidx[r] * DDIM + c0 + tx];
        __syncthreads();
        #pragma unroll
        for (int cy = ty; cy < 32; cy += 8) {
            int c = c0 + cy;
            size_t oi = (size_t)b * (DDIM * HWSZ) + (size_t)c * HWSZ + hw0 + tx;
            float zv = z[oi];
            float zq = esm[tx][cy];
            float df = zq - zv;          // fp32, as in reference
            out[oi] = zv + df;           // z + sg(z_q - z)
            float sq = df * df;
            acc += (double)sq;
        }
    }
    red[threadIdx.x] = acc;
    __syncthreads();
    for (int o = 128; o > 0; o >>= 1) {
        if (threadIdx.x < o) red[threadIdx.x] += red[threadIdx.x + o];
        __syncthreads();
    }
    if (threadIdx.x == 0) g_loss_part[blockIdx.x] = red[0];
}

// ======== finalize: loss + perplexity ========
__global__ void vq_fin_kernel(float* out_loss, float* out_perp, int write) {
    __shared__ double red[1024];
    int tid = threadIdx.x;

    red[tid] = (tid < OUT_BLK) ? g_loss_part[tid] : 0.0;
    __syncthreads();
    for (int o = 512; o > 0; o >>= 1) {
        if (tid < o) red[tid] += red[tid + o];
        __syncthreads();
    }
    if (tid == 0 && write) {
        double m = red[0] / (double)Z_ELEMS;
        float mf = (float)m;
        out_loss[0] = mf + 0.25f * mf;
    }
    __syncthreads();

    double p_s = 0.0;
    for (int t = 0; t < 8; t++) {
        int c = g_counts[tid * 8 + t];
        double p = (double)c * (1.0 / 8192.0);
        p_s += p * log(p + 1e-10);
    }
    red[tid] = p_s;
    __syncthreads();
    for (int o = 512; o > 0; o >>= 1) {
        if (tid < o) red[tid] += red[tid + o];
        __syncthreads();
    }
    if (tid == 0 && write) out_perp[0] = (float)exp(-red[0]);
}

extern "C" void kernel_launch(void* const* d_in, const int* in_sizes, int n_in,
                              void* d_out, int out_size) {
    const float* z = (const float*)d_in[0];
    const float* e = (const float*)d_in[1];
    float* out = (float*)d_out;

    int has_scalars = (out_size >= Z_ELEMS + 2);
    int has_idx     = (out_size >= Z_ELEMS + 2 + NVEC);

    vq_pre_kernel<<<11328, 256>>>(z, e);
    vq_gemm_kernel<<<dim3(KEMB / 128, NVEC / 128), 256>>>();
    vq_scan_kernel<<<NVEC, 256>>>();
    vq_exact_kernel<<<NVEC / 8, 256>>>(e);
    vq_idx_kernel<<<NVEC / 256, 256>>>(
        has_idx ? out + Z_ELEMS + 2 : (float*)d_out, has_idx);
    vq_out_kernel<<<OUT_BLK, 256>>>(z, e, out);
    vq_fin_kernel<<<1, 1024>>>(
        has_scalars ? out + Z_ELEMS : (float*)d_out,
        has_scalars ? out + Z_ELEMS + 1 : (float*)d_out, has_scalars);
}